// round 9
// baseline (speedup 1.0000x reference)
#include <cuda_runtime.h>
#include <float.h>
#include <stdint.h>

#define BB 2
#define HH 12
#define NN 1600
#define DD 32
#define GG 48
#define KT 96
#define CC 384
#define BHc (BB*HH)          // 24
#define NQ (BHc*NN)          // 38400
#define NROW (BHc*GG)        // 1152

// Scratch (no cudaMalloc allowed)
__device__ float g_qkv[3][BHc*NN*DD];      // [which][b*h][n][d]
__device__ int   g_gidx[NQ];
__device__ float g_qsum[NROW*DD];
__device__ int   g_cnt[NROW];
__device__ int   g_topk[NROW*KT];
__device__ int   g_qlist[NROW*NN];         // query indices per (bh,g)
__device__ float g_att[BB*NN*HH*DD];       // [b][n][h][d]
__device__ unsigned g_scores[NROW*NN];     // f2u-mapped qmw scores

__global__ void zero_kernel() {
    int i = blockIdx.x*blockDim.x + threadIdx.x;
    if (i < NROW*DD) g_qsum[i] = 0.f;
    if (i < NROW)    g_cnt[i] = 0;
}

// ---------------- 3xTF32 mma.sync GEMM ----------------
__device__ __forceinline__ uint32_t tf32_rna(float x) {
    uint32_t r; asm("cvt.rna.tf32.f32 %0, %1;" : "=r"(r) : "f"(x)); return r;
}
__device__ __forceinline__ void split_tf32(float x, uint32_t& h, uint32_t& l) {
    h = tf32_rna(x);
    l = tf32_rna(x - __uint_as_float(h));
}
__device__ __forceinline__ void mma8(float* c, const uint32_t* a, const uint32_t* b) {
    asm volatile(
        "mma.sync.aligned.m16n8k8.row.col.f32.tf32.tf32.f32 "
        "{%0,%1,%2,%3}, {%4,%5,%6,%7}, {%8,%9}, {%0,%1,%2,%3};"
        : "+f"(c[0]), "+f"(c[1]), "+f"(c[2]), "+f"(c[3])
        : "r"(a[0]), "r"(a[1]), "r"(a[2]), "r"(a[3]), "r"(b[0]), "r"(b[1]));
}

// out[m][col] = sum_k A[m][k] * B[col][k]   (NT, K=384)
// MODE 0: A = x, scatter into g_qkv.  MODE 1: A = g_att, write d_out.
// C tile 128x128 per block, 8 warps in 2(m)x4(n), warp tile 64x32.
// fp32 = tf32_hi + tf32_lo stored PRE-SPLIT in smem as uint2(hi,lo);
// acc += ah*bh + ah*bl + al*bh.  Register prefetch of the next k-tile.
#define GSTRIDE 36
#define GM_SMEM_BYTES (2 * 128 * GSTRIDE * 8)
#define AS2(r, c) smem2[(r)*GSTRIDE + (c)]
#define BS2(r, c) smem2[128*GSTRIDE + (r)*GSTRIDE + (c)]

template<int MODE>
__global__ void __launch_bounds__(256, 1) gemm_tf32(const float* __restrict__ A,
                                                    const float* __restrict__ B,
                                                    float* __restrict__ out) {
    extern __shared__ uint2 smem2[];
    const int K = CC;
    const float* Ap = (MODE == 0) ? A : (const float*)g_att;
    int m0 = blockIdx.y * 128, n0 = blockIdx.x * 128;
    int tid = threadIdx.x, wid = tid >> 5, lane = tid & 31;
    int warpM = (wid >> 2) * 64;     // 0 or 64
    int warpN = (wid & 3) * 32;      // 0,32,64,96

    float acc[4][4][4];
    #pragma unroll
    for (int i = 0; i < 4; i++)
        #pragma unroll
        for (int j = 0; j < 4; j++)
            #pragma unroll
            for (int r = 0; r < 4; r++) acc[i][j][r] = 0.f;

    int srow = tid >> 3, sc4 = (tid & 7) << 2;
    float4 pa[4], pb[4];
    #pragma unroll
    for (int it = 0; it < 4; it++) {
        int row = it*32 + srow;
        pa[it] = *(const float4*)(Ap + (size_t)(m0 + row)*K + sc4);
        pb[it] = *(const float4*)(B  + (size_t)(n0 + row)*K + sc4);
    }

    const int NT = K / 32;   // 12
    for (int kt = 0; kt < NT; kt++) {
        // split prefetched tile into smem (hi,lo interleaved)
        #pragma unroll
        for (int it = 0; it < 4; it++) {
            int row = it*32 + srow;
            uint32_t h0,l0,h1,l1,h2,l2,h3,l3;
            split_tf32(pa[it].x, h0, l0); split_tf32(pa[it].y, h1, l1);
            split_tf32(pa[it].z, h2, l2); split_tf32(pa[it].w, h3, l3);
            *(uint4*)&AS2(row, sc4)     = make_uint4(h0, l0, h1, l1);
            *(uint4*)&AS2(row, sc4 + 2) = make_uint4(h2, l2, h3, l3);
            split_tf32(pb[it].x, h0, l0); split_tf32(pb[it].y, h1, l1);
            split_tf32(pb[it].z, h2, l2); split_tf32(pb[it].w, h3, l3);
            *(uint4*)&BS2(row, sc4)     = make_uint4(h0, l0, h1, l1);
            *(uint4*)&BS2(row, sc4 + 2) = make_uint4(h2, l2, h3, l3);
        }
        __syncthreads();
        if (kt + 1 < NT) {
            int k0 = (kt + 1) * 32;
            #pragma unroll
            for (int it = 0; it < 4; it++) {
                int row = it*32 + srow;
                pa[it] = *(const float4*)(Ap + (size_t)(m0 + row)*K + k0 + sc4);
                pb[it] = *(const float4*)(B  + (size_t)(n0 + row)*K + k0 + sc4);
            }
        }
        #pragma unroll
        for (int kk = 0; kk < 4; kk++) {
            int c = kk*8 + (lane & 3);
            uint32_t ah[4][4], al[4][4], bh[4][2], bl[4][2];
            #pragma unroll
            for (int fm = 0; fm < 4; fm++) {
                int r = warpM + fm*16 + (lane >> 2);
                uint2 v0 = AS2(r, c), v1 = AS2(r + 8, c);
                uint2 v2 = AS2(r, c + 4), v3 = AS2(r + 8, c + 4);
                ah[fm][0] = v0.x; al[fm][0] = v0.y;
                ah[fm][1] = v1.x; al[fm][1] = v1.y;
                ah[fm][2] = v2.x; al[fm][2] = v2.y;
                ah[fm][3] = v3.x; al[fm][3] = v3.y;
            }
            #pragma unroll
            for (int fn = 0; fn < 4; fn++) {
                int n = warpN + fn*8 + (lane >> 2);
                uint2 w0 = BS2(n, c), w1 = BS2(n, c + 4);
                bh[fn][0] = w0.x; bl[fn][0] = w0.y;
                bh[fn][1] = w1.x; bl[fn][1] = w1.y;
            }
            #pragma unroll
            for (int fm = 0; fm < 4; fm++)
                #pragma unroll
                for (int fn = 0; fn < 4; fn++)
                    mma8(acc[fm][fn], ah[fm], bh[fn]);
            #pragma unroll
            for (int fm = 0; fm < 4; fm++)
                #pragma unroll
                for (int fn = 0; fn < 4; fn++)
                    mma8(acc[fm][fn], ah[fm], bl[fn]);
            #pragma unroll
            for (int fm = 0; fm < 4; fm++)
                #pragma unroll
                for (int fn = 0; fn < 4; fn++)
                    mma8(acc[fm][fn], al[fm], bh[fn]);
        }
        __syncthreads();
    }

    // epilogue: c0,c1 -> (m, n),(m, n+1); c2,c3 -> (m+8, n),(m+8, n+1)
    #pragma unroll
    for (int fm = 0; fm < 4; fm++) {
        #pragma unroll
        for (int half = 0; half < 2; half++) {
            int m = m0 + warpM + fm*16 + (lane >> 2) + half*8;
            int bi = m / NN, n = m % NN;
            #pragma unroll
            for (int fn = 0; fn < 4; fn++) {
                int col = n0 + warpN + fn*8 + 2*(lane & 3);
                float v0 = acc[fm][fn][half*2 + 0];
                float v1 = acc[fm][fn][half*2 + 1];
                if (MODE == 0) {
                    int which = col / (HH*DD);
                    int r2 = col % (HH*DD);
                    int head = r2 / DD, dd = r2 % DD;
                    float* dst = &g_qkv[which][(((size_t)bi*HH + head)*NN + n)*DD + dd];
                    *(float2*)dst = make_float2(v0, v1);
                } else {
                    *(float2*)&out[(size_t)m*(HH*DD) + col] = make_float2(v0, v1);
                }
            }
        }
    }
}

// One warp per query. Lane-per-group argmax (first-max tie-break = jnp.argmax),
// accumulate group sums/counts, append query to its group's list.
__global__ void route_kernel(const float* __restrict__ w_gp) {
    __shared__ float sgp[GG][33];
    int tid = threadIdx.x;
    int qid = blockIdx.x * 8 + (tid >> 5);
    int lane = tid & 31;
    int bh = qid / NN, n = qid % NN;
    int h = bh % HH;
    for (int i = tid; i < GG*DD; i += 256)
        sgp[i >> 5][i & 31] = w_gp[h*GG*DD + i];
    __syncthreads();
    float qv = g_qkv[0][((size_t)bh*NN + n)*DD + lane];
    float s0 = 0.f, s1 = 0.f;
    #pragma unroll
    for (int d = 0; d < DD; d++) {
        float qd = __shfl_sync(0xffffffffu, qv, d);
        s0 += qd * sgp[lane][d];
        if (lane < 16) s1 += qd * sgp[lane + 32][d];
    }
    float bv = s0; int bg = lane;
    if (lane < 16 && (s1 > bv)) { bv = s1; bg = lane + 32; }
    #pragma unroll
    for (int o = 16; o; o >>= 1) {
        float ov = __shfl_xor_sync(0xffffffffu, bv, o);
        int   og = __shfl_xor_sync(0xffffffffu, bg, o);
        if (ov > bv || (ov == bv && og < bg)) { bv = ov; bg = og; }
    }
    bg = __shfl_sync(0xffffffffu, bg, 0);
    int row = bh*GG + bg;
    if (lane == 0) {
        g_gidx[qid] = bg;
        int p = atomicAdd(&g_cnt[row], 1);
        g_qlist[row*NN + p] = n;
    }
    atomicAdd(&g_qsum[row*DD + lane], qv);
}

__device__ __forceinline__ unsigned f2u_mono(float f) {
    unsigned u = __float_as_uint(f);
    return u ^ (((int)u >> 31) | 0x80000000u);
}

// Grid (25, BHc): 64 keys per block; thread = (key, 12-group chunk).
__global__ void qmw_score_kernel() {
    __shared__ float qm[GG][DD];
    int bh = blockIdx.y;
    int n0 = blockIdx.x * 64;
    int tid = threadIdx.x;
    for (int i = tid; i < GG*DD; i += 256) {
        int g = i >> 5, d = i & 31;
        int row = bh*GG + g;
        float c = (float)g_cnt[row];
        qm[g][d] = g_qsum[row*DD + d] / fmaxf(c, 1e-8f);
    }
    __syncthreads();
    int key = tid & 63, gc = (tid >> 6) * 12;   // 4 chunks of 12 groups
    int m = n0 + key;
    const float* kb = &g_qkv[1][(size_t)bh*NN*DD];
    float kr[DD];
    #pragma unroll
    for (int t = 0; t < 8; t++) {
        float4 v = *(const float4*)(kb + (size_t)m*DD + 4*t);
        kr[4*t] = v.x; kr[4*t+1] = v.y; kr[4*t+2] = v.z; kr[4*t+3] = v.w;
    }
    float s[12];
    #pragma unroll
    for (int j = 0; j < 12; j++) s[j] = 0.f;
    #pragma unroll
    for (int t = 0; t < 8; t++) {
        #pragma unroll
        for (int j = 0; j < 12; j++) {
            float4 q = *(const float4*)&qm[gc + j][4*t];
            s[j] += q.x*kr[4*t] + q.y*kr[4*t+1] + q.z*kr[4*t+2] + q.w*kr[4*t+3];
        }
    }
    #pragma unroll
    for (int j = 0; j < 12; j++)
        g_scores[(size_t)(bh*GG + gc + j)*NN + m] = f2u_mono(s[j]);
}

// One block per row: radix-select top-96 from g_scores[row].
// Empty rows exit immediately (their topk list is never consumed).
__global__ void topk_select_kernel() {
    int row = blockIdx.x;
    if (g_cnt[row] == 0) return;
    __shared__ unsigned uv[NN];
    __shared__ unsigned hist[256];
    __shared__ int s_selb, s_k, s_nout;
    __shared__ int warp_sums[8];
    int tid = threadIdx.x, lane = tid & 31, w = tid >> 5;

    const unsigned* src = &g_scores[(size_t)row*NN];
    for (int m = tid; m < NN; m += 256) uv[m] = src[m];
    hist[tid] = 0;
    __syncthreads();

    unsigned prefix = 0;
    int k = KT;
    #pragma unroll
    for (int pass = 0; pass < 4; pass++) {
        int shift = 24 - 8*pass;
        for (int m = tid; m < NN; m += 256) {
            unsigned u = uv[m];
            bool cand = (pass == 0) || ((u >> (shift+8)) == (prefix >> (shift+8)));
            if (cand) atomicAdd(&hist[(u >> shift) & 255], 1u);
        }
        __syncthreads();
        if (tid < 32) {
            unsigned hv[8], loc[8];
            unsigned s = 0;
            #pragma unroll
            for (int i = 7; i >= 0; i--) {
                hv[i] = hist[lane*8 + i];
                s += hv[i];
                loc[i] = s;
            }
            unsigned run = s;
            #pragma unroll
            for (int o = 1; o < 32; o <<= 1) {
                unsigned t = __shfl_down_sync(0xffffffffu, run, o);
                if (lane + o < 32) run += t;
            }
            unsigned above = run - s;
            #pragma unroll
            for (int i = 0; i < 8; i++) {
                unsigned S  = above + loc[i];
                unsigned gt = S - hv[i];
                if ((unsigned)k <= S && (unsigned)k > gt) {
                    s_selb = lane*8 + i;
                    s_k    = k - (int)gt;
                }
            }
        }
        __syncthreads();
        prefix |= (unsigned)s_selb << shift;
        k = s_k;
        hist[tid] = 0;
        __syncthreads();
    }
    unsigned uT = prefix;
    int k_rem = k;
    if (tid == 0) s_nout = 0;
    __syncthreads();
    for (int m = tid; m < NN; m += 256) {
        if (uv[m] > uT) {
            int p = atomicAdd(&s_nout, 1);
            g_topk[row*KT + p] = m;
        }
    }
    __syncthreads();
    int base = s_nout;
    const int CH = (NN + 255) / 256;
    int lo = tid * CH;
    int hi = lo + CH; if (hi > NN) hi = NN; if (lo > NN) lo = NN;
    int c_loc = 0;
    for (int m = lo; m < hi; m++) if (uv[m] == uT) c_loc++;
    int v = c_loc;
    #pragma unroll
    for (int o = 1; o < 32; o <<= 1) {
        int t = __shfl_up_sync(0xffffffffu, v, o);
        if (lane >= o) v += t;
    }
    if (lane == 31) warp_sums[w] = v;
    __syncthreads();
    int woff = 0;
    #pragma unroll
    for (int ww = 0; ww < 8; ww++) if (ww < w) woff += warp_sums[ww];
    int rank = woff + v - c_loc;
    for (int m = lo; m < hi; m++) {
        if (uv[m] == uT) {
            if (rank < k_rem) g_topk[row*KT + base + rank] = m;
            rank++;
        }
    }
}

// One block per (bh,g): stage the group's 96 K/V rows in smem, then each warp
// processes queries of the group: scores + softmax + weighted V sum.
__global__ void attn_kernel() {
    int row = blockIdx.x;              // [0, NROW)
    int cnt = g_cnt[row];
    if (cnt == 0) return;
    int bh = row / GG;
    int bi = bh / HH, h = bh % HH;
    __shared__ float Kt[DD][97];       // [d][key]
    __shared__ float Vs[KT][33];       // [key][d]
    int tid = threadIdx.x, w = tid >> 5, lane = tid & 31;
    const int* tk = &g_topk[row*KT];
    const float* kb = &g_qkv[1][(size_t)bh*NN*DD];
    const float* vb = &g_qkv[2][(size_t)bh*NN*DD];
    for (int j = w; j < KT; j += 8) {
        int idx = tk[j];
        Kt[lane][j] = kb[(size_t)idx*DD + lane];
        Vs[j][lane] = vb[(size_t)idx*DD + lane];
    }
    __syncthreads();
    const int* ql = &g_qlist[row*NN];
    const float* qb = &g_qkv[0][(size_t)bh*NN*DD];
    const float scale = 0.17677669529663687f;  // 32^-0.5
    for (int i = w; i < cnt; i += 8) {
        int n = ql[i];
        float qv = qb[(size_t)n*DD + lane];
        float s0 = 0.f, s1 = 0.f, s2 = 0.f;
        #pragma unroll
        for (int d = 0; d < DD; d++) {
            float qd = __shfl_sync(0xffffffffu, qv, d);
            s0 += qd * Kt[d][lane];
            s1 += qd * Kt[d][lane + 32];
            s2 += qd * Kt[d][lane + 64];
        }
        s0 *= scale; s1 *= scale; s2 *= scale;
        float mx = fmaxf(s0, fmaxf(s1, s2));
        #pragma unroll
        for (int o = 16; o; o >>= 1) mx = fmaxf(mx, __shfl_xor_sync(0xffffffffu, mx, o));
        float e0 = __expf(s0 - mx), e1 = __expf(s1 - mx), e2 = __expf(s2 - mx);
        float ps = e0 + e1 + e2;
        #pragma unroll
        for (int o = 16; o; o >>= 1) ps += __shfl_xor_sync(0xffffffffu, ps, o);
        float inv = 1.f / ps;
        float acc = 0.f;
        #pragma unroll
        for (int j = 0; j < KT; j++) {
            float pj = __shfl_sync(0xffffffffu, (j < 32) ? e0 : ((j < 64) ? e1 : e2), j & 31);
            acc += pj * Vs[j][lane];
        }
        acc *= inv;
        g_att[(((size_t)bi*NN + n)*HH + h)*DD + lane] = acc;
    }
}

extern "C" void kernel_launch(void* const* d_in, const int* in_sizes, int n_in,
                              void* d_out, int out_size) {
    const float* x      = (const float*)d_in[0];
    const float* w_qkv  = (const float*)d_in[1];
    const float* w_gp   = (const float*)d_in[2];
    const float* w_proj = (const float*)d_in[3];
    float* out = (float*)d_out;

    cudaFuncSetAttribute(gemm_tf32<0>, cudaFuncAttributeMaxDynamicSharedMemorySize, GM_SMEM_BYTES);
    cudaFuncSetAttribute(gemm_tf32<1>, cudaFuncAttributeMaxDynamicSharedMemorySize, GM_SMEM_BYTES);

    zero_kernel<<<144, 256>>>();
    gemm_tf32<0><<<dim3(9, 25), 256, GM_SMEM_BYTES>>>(x, w_qkv, nullptr);    // QKV: 3200x1152x384
    route_kernel<<<NQ/8, 256>>>(w_gp);
    qmw_score_kernel<<<dim3(25, BHc), 256>>>();
    topk_select_kernel<<<NROW, 256>>>();
    attn_kernel<<<NROW, 256>>>();
    gemm_tf32<1><<<dim3(3, 25), 256, GM_SMEM_BYTES>>>(nullptr, w_proj, out); // proj: 3200x384x384
}

// round 10
// speedup vs baseline: 1.1091x; 1.1091x over previous
#include <cuda_runtime.h>
#include <float.h>
#include <stdint.h>

#define BB 2
#define HH 12
#define NN 1600
#define DD 32
#define GG 48
#define KT 96
#define CC 384
#define BHc (BB*HH)          // 24
#define NQ (BHc*NN)          // 38400
#define NROW (BHc*GG)        // 1152

// Scratch (no cudaMalloc allowed)
__device__ float g_qkv[3][BHc*NN*DD];      // [which][b*h][n][d]
__device__ int   g_gidx[NQ];
__device__ float g_qsum[NROW*DD];
__device__ int   g_cnt[NROW];
__device__ int   g_qlist[NROW*NN];         // query indices per (bh,g)
__device__ float g_att[BB*NN*HH*DD];       // [b][n][h][d]
__device__ unsigned g_scores[NROW*NN];     // f2u-mapped qmw scores

__global__ void zero_kernel() {
    int i = blockIdx.x*blockDim.x + threadIdx.x;
    if (i < NROW*DD) g_qsum[i] = 0.f;
    if (i < NROW)    g_cnt[i] = 0;
}

// ---------------- 3xTF32 mma.sync GEMM (R7 version — do not touch) ----------------
__device__ __forceinline__ uint32_t tf32_rna(float x) {
    uint32_t r; asm("cvt.rna.tf32.f32 %0, %1;" : "=r"(r) : "f"(x)); return r;
}
__device__ __forceinline__ void split_tf32(float x, uint32_t& h, uint32_t& l) {
    h = tf32_rna(x);
    l = tf32_rna(x - __uint_as_float(h));
}
__device__ __forceinline__ void mma8(float* c, const uint32_t* a, const uint32_t* b) {
    asm volatile(
        "mma.sync.aligned.m16n8k8.row.col.f32.tf32.tf32.f32 "
        "{%0,%1,%2,%3}, {%4,%5,%6,%7}, {%8,%9}, {%0,%1,%2,%3};"
        : "+f"(c[0]), "+f"(c[1]), "+f"(c[2]), "+f"(c[3])
        : "r"(a[0]), "r"(a[1]), "r"(a[2]), "r"(a[3]), "r"(b[0]), "r"(b[1]));
}

// out[m][col] = sum_k A[m][k] * B[col][k]   (NT, K=384)
// MODE 0: A = x, scatter into g_qkv.  MODE 1: A = g_att, write d_out.
template<int MODE>
__global__ void __launch_bounds__(256, 1) gemm_tf32(const float* __restrict__ A,
                                                    const float* __restrict__ B,
                                                    float* __restrict__ out) {
    __shared__ float As[128][36];    // [m][k], stride 36 -> conflict-free frag loads
    __shared__ float Bs[128][36];    // [n][k]
    const int K = CC;
    const float* Ap = (MODE == 0) ? A : (const float*)g_att;
    int m0 = blockIdx.y * 128, n0 = blockIdx.x * 128;
    int tid = threadIdx.x, wid = tid >> 5, lane = tid & 31;
    int warpM = (wid >> 2) * 64;     // 0 or 64
    int warpN = (wid & 3) * 32;      // 0,32,64,96

    float acc[4][4][4];
    #pragma unroll
    for (int i = 0; i < 4; i++)
        #pragma unroll
        for (int j = 0; j < 4; j++)
            #pragma unroll
            for (int r = 0; r < 4; r++) acc[i][j][r] = 0.f;

    int srow = tid >> 3, sc4 = (tid & 7) << 2;
    for (int kt = 0; kt < K/32; kt++) {
        int k0 = kt * 32;
        #pragma unroll
        for (int it = 0; it < 4; it++) {
            int row = it*32 + srow;
            float4 va = *(const float4*)(Ap + (size_t)(m0 + row)*K + k0 + sc4);
            float4 vb = *(const float4*)(B  + (size_t)(n0 + row)*K + k0 + sc4);
            *(float4*)&As[row][sc4] = va;
            *(float4*)&Bs[row][sc4] = vb;
        }
        __syncthreads();
        #pragma unroll
        for (int kk = 0; kk < 4; kk++) {
            int c = kk*8 + (lane & 3);
            uint32_t ah[4][4], al[4][4], bh[4][2], bl[4][2];
            #pragma unroll
            for (int fm = 0; fm < 4; fm++) {
                int r = warpM + fm*16 + (lane >> 2);
                split_tf32(As[r    ][c    ], ah[fm][0], al[fm][0]);
                split_tf32(As[r + 8][c    ], ah[fm][1], al[fm][1]);
                split_tf32(As[r    ][c + 4], ah[fm][2], al[fm][2]);
                split_tf32(As[r + 8][c + 4], ah[fm][3], al[fm][3]);
            }
            #pragma unroll
            for (int fn = 0; fn < 4; fn++) {
                int n = warpN + fn*8 + (lane >> 2);
                split_tf32(Bs[n][c    ], bh[fn][0], bl[fn][0]);
                split_tf32(Bs[n][c + 4], bh[fn][1], bl[fn][1]);
            }
            #pragma unroll
            for (int fm = 0; fm < 4; fm++)
                #pragma unroll
                for (int fn = 0; fn < 4; fn++)
                    mma8(acc[fm][fn], ah[fm], bh[fn]);
            #pragma unroll
            for (int fm = 0; fm < 4; fm++)
                #pragma unroll
                for (int fn = 0; fn < 4; fn++)
                    mma8(acc[fm][fn], ah[fm], bl[fn]);
            #pragma unroll
            for (int fm = 0; fm < 4; fm++)
                #pragma unroll
                for (int fn = 0; fn < 4; fn++)
                    mma8(acc[fm][fn], al[fm], bh[fn]);
        }
        __syncthreads();
    }

    // epilogue: c0,c1 -> (m, n),(m, n+1); c2,c3 -> (m+8, n),(m+8, n+1)
    #pragma unroll
    for (int fm = 0; fm < 4; fm++) {
        #pragma unroll
        for (int half = 0; half < 2; half++) {
            int m = m0 + warpM + fm*16 + (lane >> 2) + half*8;
            int bi = m / NN, n = m % NN;
            #pragma unroll
            for (int fn = 0; fn < 4; fn++) {
                int col = n0 + warpN + fn*8 + 2*(lane & 3);
                float v0 = acc[fm][fn][half*2 + 0];
                float v1 = acc[fm][fn][half*2 + 1];
                if (MODE == 0) {
                    int which = col / (HH*DD);
                    int r2 = col % (HH*DD);
                    int head = r2 / DD, dd = r2 % DD;
                    float* dst = &g_qkv[which][(((size_t)bi*HH + head)*NN + n)*DD + dd];
                    *(float2*)dst = make_float2(v0, v1);
                } else {
                    *(float2*)&out[(size_t)m*(HH*DD) + col] = make_float2(v0, v1);
                }
            }
        }
    }
}

// One warp per query. Lane-per-group argmax (first-max tie-break = jnp.argmax),
// accumulate group sums/counts, append query to its group's list.
__global__ void route_kernel(const float* __restrict__ w_gp) {
    __shared__ float sgp[GG][33];
    int tid = threadIdx.x;
    int qid = blockIdx.x * 8 + (tid >> 5);
    int lane = tid & 31;
    int bh = qid / NN, n = qid % NN;
    int h = bh % HH;
    for (int i = tid; i < GG*DD; i += 256)
        sgp[i >> 5][i & 31] = w_gp[h*GG*DD + i];
    __syncthreads();
    float qv = g_qkv[0][((size_t)bh*NN + n)*DD + lane];
    float s0 = 0.f, s1 = 0.f;
    #pragma unroll
    for (int d = 0; d < DD; d++) {
        float qd = __shfl_sync(0xffffffffu, qv, d);
        s0 += qd * sgp[lane][d];
        if (lane < 16) s1 += qd * sgp[lane + 32][d];
    }
    float bv = s0; int bg = lane;
    if (lane < 16 && (s1 > bv)) { bv = s1; bg = lane + 32; }
    #pragma unroll
    for (int o = 16; o; o >>= 1) {
        float ov = __shfl_xor_sync(0xffffffffu, bv, o);
        int   og = __shfl_xor_sync(0xffffffffu, bg, o);
        if (ov > bv || (ov == bv && og < bg)) { bv = ov; bg = og; }
    }
    bg = __shfl_sync(0xffffffffu, bg, 0);
    int row = bh*GG + bg;
    if (lane == 0) {
        g_gidx[qid] = bg;
        int p = atomicAdd(&g_cnt[row], 1);
        g_qlist[row*NN + p] = n;
    }
    atomicAdd(&g_qsum[row*DD + lane], qv);
}

__device__ __forceinline__ unsigned f2u_mono(float f) {
    unsigned u = __float_as_uint(f);
    return u ^ (((int)u >> 31) | 0x80000000u);
}

// Grid (25, BHc): 64 keys per block; thread = (key, 12-group chunk).
__global__ void qmw_score_kernel() {
    __shared__ float qm[GG][DD];
    int bh = blockIdx.y;
    int n0 = blockIdx.x * 64;
    int tid = threadIdx.x;
    for (int i = tid; i < GG*DD; i += 256) {
        int g = i >> 5, d = i & 31;
        int row = bh*GG + g;
        float c = (float)g_cnt[row];
        qm[g][d] = g_qsum[row*DD + d] / fmaxf(c, 1e-8f);
    }
    __syncthreads();
    int key = tid & 63, gc = (tid >> 6) * 12;   // 4 chunks of 12 groups
    int m = n0 + key;
    const float* kb = &g_qkv[1][(size_t)bh*NN*DD];
    float kr[DD];
    #pragma unroll
    for (int t = 0; t < 8; t++) {
        float4 v = *(const float4*)(kb + (size_t)m*DD + 4*t);
        kr[4*t] = v.x; kr[4*t+1] = v.y; kr[4*t+2] = v.z; kr[4*t+3] = v.w;
    }
    float s[12];
    #pragma unroll
    for (int j = 0; j < 12; j++) s[j] = 0.f;
    #pragma unroll
    for (int t = 0; t < 8; t++) {
        #pragma unroll
        for (int j = 0; j < 12; j++) {
            float4 q = *(const float4*)&qm[gc + j][4*t];
            s[j] += q.x*kr[4*t] + q.y*kr[4*t+1] + q.z*kr[4*t+2] + q.w*kr[4*t+3];
        }
    }
    #pragma unroll
    for (int j = 0; j < 12; j++)
        g_scores[(size_t)(bh*GG + gc + j)*NN + m] = f2u_mono(s[j]);
}

// Fused: one block per (bh,g) row — radix-select top-96 from g_scores[row]
// (indices kept in smem), then stage the 96 K/V rows and run attention for
// all queries of the group. Empty rows exit immediately.
__global__ void select_attn_kernel() {
    int row = blockIdx.x;              // [0, NROW)
    int cnt = g_cnt[row];
    if (cnt == 0) return;

    __shared__ unsigned uv[NN];
    __shared__ unsigned hist[256];
    __shared__ int s_selb, s_k, s_nout;
    __shared__ int warp_sums[8];
    __shared__ int tk_s[KT];
    __shared__ float Kt[DD][97];       // [d][key]
    __shared__ float Vs[KT][33];       // [key][d]

    int tid = threadIdx.x, lane = tid & 31, w = tid >> 5;

    // ---- selection phase (identical logic to previous topk_select) ----
    const unsigned* src = &g_scores[(size_t)row*NN];
    for (int m = tid; m < NN; m += 256) uv[m] = src[m];
    hist[tid] = 0;
    __syncthreads();

    unsigned prefix = 0;
    int k = KT;
    #pragma unroll
    for (int pass = 0; pass < 4; pass++) {
        int shift = 24 - 8*pass;
        for (int m = tid; m < NN; m += 256) {
            unsigned u = uv[m];
            bool cand = (pass == 0) || ((u >> (shift+8)) == (prefix >> (shift+8)));
            if (cand) atomicAdd(&hist[(u >> shift) & 255], 1u);
        }
        __syncthreads();
        if (tid < 32) {
            unsigned hv[8], loc[8];
            unsigned s = 0;
            #pragma unroll
            for (int i = 7; i >= 0; i--) {
                hv[i] = hist[lane*8 + i];
                s += hv[i];
                loc[i] = s;
            }
            unsigned run = s;
            #pragma unroll
            for (int o = 1; o < 32; o <<= 1) {
                unsigned t = __shfl_down_sync(0xffffffffu, run, o);
                if (lane + o < 32) run += t;
            }
            unsigned above = run - s;  // count in lanes > me
            #pragma unroll
            for (int i = 0; i < 8; i++) {
                unsigned S  = above + loc[i];           // count >= bin
                unsigned gt = S - hv[i];                // count > bin
                if ((unsigned)k <= S && (unsigned)k > gt) {
                    s_selb = lane*8 + i;
                    s_k    = k - (int)gt;
                }
            }
        }
        __syncthreads();
        prefix |= (unsigned)s_selb << shift;
        k = s_k;
        hist[tid] = 0;                 // re-zero for next pass
        __syncthreads();
    }
    unsigned uT = prefix;
    int k_rem = k;
    if (tid == 0) s_nout = 0;
    __syncthreads();
    // strictly-greater: order is irrelevant (mask semantics)
    for (int m = tid; m < NN; m += 256) {
        if (uv[m] > uT) {
            int p = atomicAdd(&s_nout, 1);
            tk_s[p] = m;
        }
    }
    __syncthreads();
    int base = s_nout;                 // == KT - k_rem
    // equals: keep the k_rem LOWEST indices (lax.top_k stable tie-break).
    const int CH = (NN + 255) / 256;   // 7
    int lo = tid * CH;
    int hi = lo + CH; if (hi > NN) hi = NN; if (lo > NN) lo = NN;
    int c_loc = 0;
    for (int m = lo; m < hi; m++) if (uv[m] == uT) c_loc++;
    int v = c_loc;
    #pragma unroll
    for (int o = 1; o < 32; o <<= 1) {
        int t = __shfl_up_sync(0xffffffffu, v, o);
        if (lane >= o) v += t;
    }
    if (lane == 31) warp_sums[w] = v;
    __syncthreads();
    int woff = 0;
    #pragma unroll
    for (int ww = 0; ww < 8; ww++) if (ww < w) woff += warp_sums[ww];
    int rank = woff + v - c_loc;       // exclusive prefix in index order
    for (int m = lo; m < hi; m++) {
        if (uv[m] == uT) {
            if (rank < k_rem) tk_s[base + rank] = m;
            rank++;
        }
    }
    __syncthreads();

    // ---- attention phase (identical math to previous attn_kernel) ----
    int bh = row / GG;
    int bi = bh / HH, h = bh % HH;
    const float* kb = &g_qkv[1][(size_t)bh*NN*DD];
    const float* vb = &g_qkv[2][(size_t)bh*NN*DD];
    for (int j = w; j < KT; j += 8) {
        int idx = tk_s[j];
        Kt[lane][j] = kb[(size_t)idx*DD + lane];
        Vs[j][lane] = vb[(size_t)idx*DD + lane];
    }
    __syncthreads();
    const int* ql = &g_qlist[row*NN];
    const float* qb = &g_qkv[0][(size_t)bh*NN*DD];
    const float scale = 0.17677669529663687f;  // 32^-0.5
    for (int i = w; i < cnt; i += 8) {
        int n = ql[i];
        float qv = qb[(size_t)n*DD + lane];
        float s0 = 0.f, s1 = 0.f, s2 = 0.f;
        #pragma unroll
        for (int d = 0; d < DD; d++) {
            float qd = __shfl_sync(0xffffffffu, qv, d);
            s0 += qd * Kt[d][lane];
            s1 += qd * Kt[d][lane + 32];
            s2 += qd * Kt[d][lane + 64];
        }
        s0 *= scale; s1 *= scale; s2 *= scale;
        float mx = fmaxf(s0, fmaxf(s1, s2));
        #pragma unroll
        for (int o = 16; o; o >>= 1) mx = fmaxf(mx, __shfl_xor_sync(0xffffffffu, mx, o));
        float e0 = __expf(s0 - mx), e1 = __expf(s1 - mx), e2 = __expf(s2 - mx);
        float ps = e0 + e1 + e2;
        #pragma unroll
        for (int o = 16; o; o >>= 1) ps += __shfl_xor_sync(0xffffffffu, ps, o);
        float inv = 1.f / ps;
        float acc = 0.f;
        #pragma unroll
        for (int j = 0; j < KT; j++) {
            float pj = __shfl_sync(0xffffffffu, (j < 32) ? e0 : ((j < 64) ? e1 : e2), j & 31);
            acc += pj * Vs[j][lane];
        }
        acc *= inv;
        g_att[(((size_t)bi*NN + n)*HH + h)*DD + lane] = acc;
    }
}

extern "C" void kernel_launch(void* const* d_in, const int* in_sizes, int n_in,
                              void* d_out, int out_size) {
    const float* x      = (const float*)d_in[0];
    const float* w_qkv  = (const float*)d_in[1];
    const float* w_gp   = (const float*)d_in[2];
    const float* w_proj = (const float*)d_in[3];
    float* out = (float*)d_out;

    zero_kernel<<<144, 256>>>();
    gemm_tf32<0><<<dim3(9, 25), 256>>>(x, w_qkv, nullptr);       // QKV: 3200x1152x384
    route_kernel<<<NQ/8, 256>>>(w_gp);
    qmw_score_kernel<<<dim3(25, BHc), 256>>>();
    select_attn_kernel<<<NROW, 256>>>();
    gemm_tf32<1><<<dim3(3, 25), 256>>>(nullptr, w_proj, out);    // proj: 3200x384x384
}

// round 11
// speedup vs baseline: 1.1293x; 1.0182x over previous
#include <cuda_runtime.h>
#include <float.h>
#include <stdint.h>

#define BB 2
#define HH 12
#define NN 1600
#define DD 32
#define GG 48
#define KT 96
#define CC 384
#define BHc (BB*HH)          // 24
#define NQ (BHc*NN)          // 38400
#define NROW (BHc*GG)        // 1152

// Scratch (no cudaMalloc allowed)
__device__ float g_qkv[3][BHc*NN*DD];      // [which][b*h][n][d]
__device__ int   g_gidx[NQ];
__device__ float g_qsum[NROW*DD];
__device__ int   g_cnt[NROW];
__device__ int   g_qlist[NROW*NN];         // query indices per (bh,g)
__device__ float g_att[BB*NN*HH*DD];       // [b][n][h][d]
__device__ unsigned g_scores[NROW*NN];     // f2u-mapped qmw scores

// ---------------- 3xTF32 mma.sync GEMM (R7 version — do not touch core) -------
__device__ __forceinline__ uint32_t tf32_rna(float x) {
    uint32_t r; asm("cvt.rna.tf32.f32 %0, %1;" : "=r"(r) : "f"(x)); return r;
}
__device__ __forceinline__ void split_tf32(float x, uint32_t& h, uint32_t& l) {
    h = tf32_rna(x);
    l = tf32_rna(x - __uint_as_float(h));
}
__device__ __forceinline__ void mma8(float* c, const uint32_t* a, const uint32_t* b) {
    asm volatile(
        "mma.sync.aligned.m16n8k8.row.col.f32.tf32.tf32.f32 "
        "{%0,%1,%2,%3}, {%4,%5,%6,%7}, {%8,%9}, {%0,%1,%2,%3};"
        : "+f"(c[0]), "+f"(c[1]), "+f"(c[2]), "+f"(c[3])
        : "r"(a[0]), "r"(a[1]), "r"(a[2]), "r"(a[3]), "r"(b[0]), "r"(b[1]));
}

// out[m][col] = sum_k A[m][k] * B[col][k]   (NT, K=384)
// MODE 0: A = x, scatter into g_qkv; also zero-inits g_qsum/g_cnt (consumed
//         only by the later route_kernel, so ordering is safe).
// MODE 1: A = g_att, write d_out.
template<int MODE>
__global__ void __launch_bounds__(256, 1) gemm_tf32(const float* __restrict__ A,
                                                    const float* __restrict__ B,
                                                    float* __restrict__ out) {
    __shared__ float As[128][36];    // [m][k], stride 36 -> conflict-free frag loads
    __shared__ float Bs[128][36];    // [n][k]
    const int K = CC;
    const float* Ap = (MODE == 0) ? A : (const float*)g_att;
    int m0 = blockIdx.y * 128, n0 = blockIdx.x * 128;
    int tid = threadIdx.x, wid = tid >> 5, lane = tid & 31;
    int warpM = (wid >> 2) * 64;     // 0 or 64
    int warpN = (wid & 3) * 32;      // 0,32,64,96

    if (MODE == 0) {
        // folded zero-init (225 blocks x 256 threads >= NROW*DD)
        int zi = (blockIdx.y * 9 + blockIdx.x) * 256 + tid;
        if (zi < NROW*DD) g_qsum[zi] = 0.f;
        if (zi < NROW)    g_cnt[zi] = 0;
    }

    float acc[4][4][4];
    #pragma unroll
    for (int i = 0; i < 4; i++)
        #pragma unroll
        for (int j = 0; j < 4; j++)
            #pragma unroll
            for (int r = 0; r < 4; r++) acc[i][j][r] = 0.f;

    int srow = tid >> 3, sc4 = (tid & 7) << 2;
    for (int kt = 0; kt < K/32; kt++) {
        int k0 = kt * 32;
        #pragma unroll
        for (int it = 0; it < 4; it++) {
            int row = it*32 + srow;
            float4 va = *(const float4*)(Ap + (size_t)(m0 + row)*K + k0 + sc4);
            float4 vb = *(const float4*)(B  + (size_t)(n0 + row)*K + k0 + sc4);
            *(float4*)&As[row][sc4] = va;
            *(float4*)&Bs[row][sc4] = vb;
        }
        __syncthreads();
        #pragma unroll
        for (int kk = 0; kk < 4; kk++) {
            int c = kk*8 + (lane & 3);
            uint32_t ah[4][4], al[4][4], bh[4][2], bl[4][2];
            #pragma unroll
            for (int fm = 0; fm < 4; fm++) {
                int r = warpM + fm*16 + (lane >> 2);
                split_tf32(As[r    ][c    ], ah[fm][0], al[fm][0]);
                split_tf32(As[r + 8][c    ], ah[fm][1], al[fm][1]);
                split_tf32(As[r    ][c + 4], ah[fm][2], al[fm][2]);
                split_tf32(As[r + 8][c + 4], ah[fm][3], al[fm][3]);
            }
            #pragma unroll
            for (int fn = 0; fn < 4; fn++) {
                int n = warpN + fn*8 + (lane >> 2);
                split_tf32(Bs[n][c    ], bh[fn][0], bl[fn][0]);
                split_tf32(Bs[n][c + 4], bh[fn][1], bl[fn][1]);
            }
            #pragma unroll
            for (int fm = 0; fm < 4; fm++)
                #pragma unroll
                for (int fn = 0; fn < 4; fn++)
                    mma8(acc[fm][fn], ah[fm], bh[fn]);
            #pragma unroll
            for (int fm = 0; fm < 4; fm++)
                #pragma unroll
                for (int fn = 0; fn < 4; fn++)
                    mma8(acc[fm][fn], ah[fm], bl[fn]);
            #pragma unroll
            for (int fm = 0; fm < 4; fm++)
                #pragma unroll
                for (int fn = 0; fn < 4; fn++)
                    mma8(acc[fm][fn], al[fm], bh[fn]);
        }
        __syncthreads();
    }

    // epilogue: c0,c1 -> (m, n),(m, n+1); c2,c3 -> (m+8, n),(m+8, n+1)
    #pragma unroll
    for (int fm = 0; fm < 4; fm++) {
        #pragma unroll
        for (int half = 0; half < 2; half++) {
            int m = m0 + warpM + fm*16 + (lane >> 2) + half*8;
            int bi = m / NN, n = m % NN;
            #pragma unroll
            for (int fn = 0; fn < 4; fn++) {
                int col = n0 + warpN + fn*8 + 2*(lane & 3);
                float v0 = acc[fm][fn][half*2 + 0];
                float v1 = acc[fm][fn][half*2 + 1];
                if (MODE == 0) {
                    int which = col / (HH*DD);
                    int r2 = col % (HH*DD);
                    int head = r2 / DD, dd = r2 % DD;
                    float* dst = &g_qkv[which][(((size_t)bi*HH + head)*NN + n)*DD + dd];
                    *(float2*)dst = make_float2(v0, v1);
                } else {
                    *(float2*)&out[(size_t)m*(HH*DD) + col] = make_float2(v0, v1);
                }
            }
        }
    }
}

// 32 queries per block (4 per warp). Lane-per-group argmax (first-max
// tie-break = jnp.argmax), accumulate group sums/counts, append to list.
__global__ void route_kernel(const float* __restrict__ w_gp) {
    __shared__ float sgp[GG][33];
    int tid = threadIdx.x;
    int w = tid >> 5, lane = tid & 31;
    int q0 = blockIdx.x * 32;          // NN % 32 == 0 -> whole block same bh
    int bh = q0 / NN;
    int h = bh % HH;
    for (int i = tid; i < GG*DD; i += 256)
        sgp[i >> 5][i & 31] = w_gp[h*GG*DD + i];
    __syncthreads();
    #pragma unroll
    for (int rep = 0; rep < 4; rep++) {
        int qid = q0 + rep*8 + w;
        int n = qid % NN;
        float qv = g_qkv[0][((size_t)bh*NN + n)*DD + lane];
        float s0 = 0.f, s1 = 0.f;
        #pragma unroll
        for (int d = 0; d < DD; d++) {
            float qd = __shfl_sync(0xffffffffu, qv, d);
            s0 += qd * sgp[lane][d];
            if (lane < 16) s1 += qd * sgp[lane + 32][d];
        }
        float bv = s0; int bg = lane;
        if (lane < 16 && (s1 > bv)) { bv = s1; bg = lane + 32; }
        #pragma unroll
        for (int o = 16; o; o >>= 1) {
            float ov = __shfl_xor_sync(0xffffffffu, bv, o);
            int   og = __shfl_xor_sync(0xffffffffu, bg, o);
            if (ov > bv || (ov == bv && og < bg)) { bv = ov; bg = og; }
        }
        bg = __shfl_sync(0xffffffffu, bg, 0);
        int row = bh*GG + bg;
        if (lane == 0) {
            g_gidx[qid] = bg;
            int p = atomicAdd(&g_cnt[row], 1);
            g_qlist[row*NN + p] = n;
        }
        atomicAdd(&g_qsum[row*DD + lane], qv);
    }
}

__device__ __forceinline__ unsigned f2u_mono(float f) {
    unsigned u = __float_as_uint(f);
    return u ^ (((int)u >> 31) | 0x80000000u);
}

// Grid (25, BHc): 64 keys per block; thread = (key, 12-group chunk).
__global__ void qmw_score_kernel() {
    __shared__ float qm[GG][DD];
    int bh = blockIdx.y;
    int n0 = blockIdx.x * 64;
    int tid = threadIdx.x;
    for (int i = tid; i < GG*DD; i += 256) {
        int g = i >> 5, d = i & 31;
        int row = bh*GG + g;
        float c = (float)g_cnt[row];
        qm[g][d] = g_qsum[row*DD + d] / fmaxf(c, 1e-8f);
    }
    __syncthreads();
    int key = tid & 63, gc = (tid >> 6) * 12;   // 4 chunks of 12 groups
    int m = n0 + key;
    const float* kb = &g_qkv[1][(size_t)bh*NN*DD];
    float kr[DD];
    #pragma unroll
    for (int t = 0; t < 8; t++) {
        float4 v = *(const float4*)(kb + (size_t)m*DD + 4*t);
        kr[4*t] = v.x; kr[4*t+1] = v.y; kr[4*t+2] = v.z; kr[4*t+3] = v.w;
    }
    float s[12];
    #pragma unroll
    for (int j = 0; j < 12; j++) s[j] = 0.f;
    #pragma unroll
    for (int t = 0; t < 8; t++) {
        #pragma unroll
        for (int j = 0; j < 12; j++) {
            float4 q = *(const float4*)&qm[gc + j][4*t];
            s[j] += q.x*kr[4*t] + q.y*kr[4*t+1] + q.z*kr[4*t+2] + q.w*kr[4*t+3];
        }
    }
    #pragma unroll
    for (int j = 0; j < 12; j++)
        g_scores[(size_t)(bh*GG + gc + j)*NN + m] = f2u_mono(s[j]);
}

// Fused: one block per (bh,g) row — radix-select top-96 from g_scores[row]
// (indices kept in smem), then stage the 96 K/V rows and run attention for
// all queries of the group. Empty rows exit immediately.
__global__ void select_attn_kernel() {
    int row = blockIdx.x;              // [0, NROW)
    int cnt = g_cnt[row];
    if (cnt == 0) return;

    __shared__ unsigned uv[NN];
    __shared__ unsigned hist[256];
    __shared__ int s_selb, s_k, s_nout;
    __shared__ int warp_sums[8];
    __shared__ int tk_s[KT];
    __shared__ float Kt[DD][97];       // [d][key]
    __shared__ float Vs[KT][33];       // [key][d]

    int tid = threadIdx.x, lane = tid & 31, w = tid >> 5;

    // ---- selection phase ----
    const unsigned* src = &g_scores[(size_t)row*NN];
    for (int m = tid; m < NN; m += 256) uv[m] = src[m];
    hist[tid] = 0;
    __syncthreads();

    unsigned prefix = 0;
    int k = KT;
    #pragma unroll
    for (int pass = 0; pass < 4; pass++) {
        int shift = 24 - 8*pass;
        for (int m = tid; m < NN; m += 256) {
            unsigned u = uv[m];
            bool cand = (pass == 0) || ((u >> (shift+8)) == (prefix >> (shift+8)));
            if (cand) atomicAdd(&hist[(u >> shift) & 255], 1u);
        }
        __syncthreads();
        if (tid < 32) {
            unsigned hv[8], loc[8];
            unsigned s = 0;
            #pragma unroll
            for (int i = 7; i >= 0; i--) {
                hv[i] = hist[lane*8 + i];
                s += hv[i];
                loc[i] = s;
            }
            unsigned run = s;
            #pragma unroll
            for (int o = 1; o < 32; o <<= 1) {
                unsigned t = __shfl_down_sync(0xffffffffu, run, o);
                if (lane + o < 32) run += t;
            }
            unsigned above = run - s;  // count in lanes > me
            #pragma unroll
            for (int i = 0; i < 8; i++) {
                unsigned S  = above + loc[i];           // count >= bin
                unsigned gt = S - hv[i];                // count > bin
                if ((unsigned)k <= S && (unsigned)k > gt) {
                    s_selb = lane*8 + i;
                    s_k    = k - (int)gt;
                }
            }
        }
        __syncthreads();
        prefix |= (unsigned)s_selb << shift;
        k = s_k;
        hist[tid] = 0;                 // re-zero for next pass
        __syncthreads();
    }
    unsigned uT = prefix;
    int k_rem = k;
    if (tid == 0) s_nout = 0;
    __syncthreads();
    // strictly-greater: order is irrelevant (mask semantics)
    for (int m = tid; m < NN; m += 256) {
        if (uv[m] > uT) {
            int p = atomicAdd(&s_nout, 1);
            tk_s[p] = m;
        }
    }
    __syncthreads();
    int base = s_nout;                 // == KT - k_rem
    // equals: keep the k_rem LOWEST indices (lax.top_k stable tie-break).
    const int CH = (NN + 255) / 256;   // 7
    int lo = tid * CH;
    int hi = lo + CH; if (hi > NN) hi = NN; if (lo > NN) lo = NN;
    int c_loc = 0;
    for (int m = lo; m < hi; m++) if (uv[m] == uT) c_loc++;
    int v = c_loc;
    #pragma unroll
    for (int o = 1; o < 32; o <<= 1) {
        int t = __shfl_up_sync(0xffffffffu, v, o);
        if (lane >= o) v += t;
    }
    if (lane == 31) warp_sums[w] = v;
    __syncthreads();
    int woff = 0;
    #pragma unroll
    for (int ww = 0; ww < 8; ww++) if (ww < w) woff += warp_sums[ww];
    int rank = woff + v - c_loc;       // exclusive prefix in index order
    for (int m = lo; m < hi; m++) {
        if (uv[m] == uT) {
            if (rank < k_rem) tk_s[base + rank] = m;
            rank++;
        }
    }
    __syncthreads();

    // ---- attention phase ----
    int bh = row / GG;
    int bi = bh / HH, h = bh % HH;
    const float* kb = &g_qkv[1][(size_t)bh*NN*DD];
    const float* vb = &g_qkv[2][(size_t)bh*NN*DD];
    for (int j = w; j < KT; j += 8) {
        int idx = tk_s[j];
        Kt[lane][j] = kb[(size_t)idx*DD + lane];
        Vs[j][lane] = vb[(size_t)idx*DD + lane];
    }
    __syncthreads();
    const int* ql = &g_qlist[row*NN];
    const float* qb = &g_qkv[0][(size_t)bh*NN*DD];
    const float scale = 0.17677669529663687f;  // 32^-0.5
    for (int i = w; i < cnt; i += 8) {
        int n = ql[i];
        float qv = qb[(size_t)n*DD + lane];
        float s0 = 0.f, s1 = 0.f, s2 = 0.f;
        #pragma unroll
        for (int d = 0; d < DD; d++) {
            float qd = __shfl_sync(0xffffffffu, qv, d);
            s0 += qd * Kt[d][lane];
            s1 += qd * Kt[d][lane + 32];
            s2 += qd * Kt[d][lane + 64];
        }
        s0 *= scale; s1 *= scale; s2 *= scale;
        float mx = fmaxf(s0, fmaxf(s1, s2));
        #pragma unroll
        for (int o = 16; o; o >>= 1) mx = fmaxf(mx, __shfl_xor_sync(0xffffffffu, mx, o));
        float e0 = __expf(s0 - mx), e1 = __expf(s1 - mx), e2 = __expf(s2 - mx);
        float ps = e0 + e1 + e2;
        #pragma unroll
        for (int o = 16; o; o >>= 1) ps += __shfl_xor_sync(0xffffffffu, ps, o);
        float inv = 1.f / ps;
        float acc = 0.f;
        #pragma unroll
        for (int j = 0; j < KT; j++) {
            float pj = __shfl_sync(0xffffffffu, (j < 32) ? e0 : ((j < 64) ? e1 : e2), j & 31);
            acc += pj * Vs[j][lane];
        }
        acc *= inv;
        g_att[(((size_t)bi*NN + n)*HH + h)*DD + lane] = acc;
    }
}

extern "C" void kernel_launch(void* const* d_in, const int* in_sizes, int n_in,
                              void* d_out, int out_size) {
    const float* x      = (const float*)d_in[0];
    const float* w_qkv  = (const float*)d_in[1];
    const float* w_gp   = (const float*)d_in[2];
    const float* w_proj = (const float*)d_in[3];
    float* out = (float*)d_out;

    gemm_tf32<0><<<dim3(9, 25), 256>>>(x, w_qkv, nullptr);       // QKV (+ zero-init)
    route_kernel<<<NQ/32, 256>>>(w_gp);
    qmw_score_kernel<<<dim3(25, BHc), 256>>>();
    select_attn_kernel<<<NROW, 256>>>();
    gemm_tf32<1><<<dim3(3, 25), 256>>>(nullptr, w_proj, out);    // proj: 3200x384x384
}

// round 14
// speedup vs baseline: 1.1842x; 1.0486x over previous
#include <cuda_runtime.h>
#include <float.h>
#include <stdint.h>

#define BB 2
#define HH 12
#define NN 1600
#define DD 32
#define GG 48
#define KT 96
#define CC 384
#define BHc (BB*HH)          // 24
#define NQ (BHc*NN)          // 38400
#define NROW (BHc*GG)        // 1152

// Scratch (no cudaMalloc allowed)
__device__ float g_qkv[3][BHc*NN*DD];      // [which][b*h][n][d]
__device__ int   g_gidx[NQ];
__device__ float g_qsum[NROW*DD];
__device__ int   g_cnt[NROW];
__device__ int   g_qlist[NROW*NN];         // query indices per (bh,g)
__device__ float g_att[BB*NN*HH*DD];       // [b][n][h][d]
__device__ unsigned g_scores[NROW*NN];     // f2u-mapped qmw scores

// ---------------- 3xTF32 mma.sync GEMM (R7 version — do not touch core) -------
__device__ __forceinline__ uint32_t tf32_rna(float x) {
    uint32_t r; asm("cvt.rna.tf32.f32 %0, %1;" : "=r"(r) : "f"(x)); return r;
}
__device__ __forceinline__ void split_tf32(float x, uint32_t& h, uint32_t& l) {
    h = tf32_rna(x);
    l = tf32_rna(x - __uint_as_float(h));
}
__device__ __forceinline__ void mma8(float* c, const uint32_t* a, const uint32_t* b) {
    asm volatile(
        "mma.sync.aligned.m16n8k8.row.col.f32.tf32.tf32.f32 "
        "{%0,%1,%2,%3}, {%4,%5,%6,%7}, {%8,%9}, {%0,%1,%2,%3};"
        : "+f"(c[0]), "+f"(c[1]), "+f"(c[2]), "+f"(c[3])
        : "r"(a[0]), "r"(a[1]), "r"(a[2]), "r"(a[3]), "r"(b[0]), "r"(b[1]));
}

// out[m][col] = sum_k A[m][k] * B[col][k]   (NT, K=384)
// MODE 0: A = x, scatter into g_qkv; also zero-inits g_qsum/g_cnt.
// MODE 1: A = g_att, write d_out.
template<int MODE>
__global__ void __launch_bounds__(256, 1) gemm_tf32(const float* __restrict__ A,
                                                    const float* __restrict__ B,
                                                    float* __restrict__ out) {
    __shared__ __align__(16) float As[128][36];
    __shared__ __align__(16) float Bs[128][36];
    const int K = CC;
    const float* Ap = (MODE == 0) ? A : (const float*)g_att;
    int m0 = blockIdx.y * 128, n0 = blockIdx.x * 128;
    int tid = threadIdx.x, wid = tid >> 5, lane = tid & 31;
    int warpM = (wid >> 2) * 64;
    int warpN = (wid & 3) * 32;

    if (MODE == 0) {
        int zi = (blockIdx.y * 9 + blockIdx.x) * 256 + tid;
        if (zi < NROW*DD) g_qsum[zi] = 0.f;
        if (zi < NROW)    g_cnt[zi] = 0;
    }

    float acc[4][4][4];
    #pragma unroll
    for (int i = 0; i < 4; i++)
        #pragma unroll
        for (int j = 0; j < 4; j++)
            #pragma unroll
            for (int r = 0; r < 4; r++) acc[i][j][r] = 0.f;

    int srow = tid >> 3, sc4 = (tid & 7) << 2;
    for (int kt = 0; kt < K/32; kt++) {
        int k0 = kt * 32;
        #pragma unroll
        for (int it = 0; it < 4; it++) {
            int row = it*32 + srow;
            float4 va = *(const float4*)(Ap + (size_t)(m0 + row)*K + k0 + sc4);
            float4 vb = *(const float4*)(B  + (size_t)(n0 + row)*K + k0 + sc4);
            *(float4*)&As[row][sc4] = va;
            *(float4*)&Bs[row][sc4] = vb;
        }
        __syncthreads();
        #pragma unroll
        for (int kk = 0; kk < 4; kk++) {
            int c = kk*8 + (lane & 3);
            uint32_t ah[4][4], al[4][4], bh[4][2], bl[4][2];
            #pragma unroll
            for (int fm = 0; fm < 4; fm++) {
                int r = warpM + fm*16 + (lane >> 2);
                split_tf32(As[r    ][c    ], ah[fm][0], al[fm][0]);
                split_tf32(As[r + 8][c    ], ah[fm][1], al[fm][1]);
                split_tf32(As[r    ][c + 4], ah[fm][2], al[fm][2]);
                split_tf32(As[r + 8][c + 4], ah[fm][3], al[fm][3]);
            }
            #pragma unroll
            for (int fn = 0; fn < 4; fn++) {
                int n = warpN + fn*8 + (lane >> 2);
                split_tf32(Bs[n][c    ], bh[fn][0], bl[fn][0]);
                split_tf32(Bs[n][c + 4], bh[fn][1], bl[fn][1]);
            }
            #pragma unroll
            for (int fm = 0; fm < 4; fm++)
                #pragma unroll
                for (int fn = 0; fn < 4; fn++)
                    mma8(acc[fm][fn], ah[fm], bh[fn]);
            #pragma unroll
            for (int fm = 0; fm < 4; fm++)
                #pragma unroll
                for (int fn = 0; fn < 4; fn++)
                    mma8(acc[fm][fn], ah[fm], bl[fn]);
            #pragma unroll
            for (int fm = 0; fm < 4; fm++)
                #pragma unroll
                for (int fn = 0; fn < 4; fn++)
                    mma8(acc[fm][fn], al[fm], bh[fn]);
        }
        __syncthreads();
    }

    #pragma unroll
    for (int fm = 0; fm < 4; fm++) {
        #pragma unroll
        for (int half = 0; half < 2; half++) {
            int m = m0 + warpM + fm*16 + (lane >> 2) + half*8;
            int bi = m / NN, n = m % NN;
            #pragma unroll
            for (int fn = 0; fn < 4; fn++) {
                int col = n0 + warpN + fn*8 + 2*(lane & 3);
                float v0 = acc[fm][fn][half*2 + 0];
                float v1 = acc[fm][fn][half*2 + 1];
                if (MODE == 0) {
                    int which = col / (HH*DD);
                    int r2 = col % (HH*DD);
                    int head = r2 / DD, dd = r2 % DD;
                    float* dst = &g_qkv[which][(((size_t)bi*HH + head)*NN + n)*DD + dd];
                    *(float2*)dst = make_float2(v0, v1);
                } else {
                    *(float2*)&out[(size_t)m*(HH*DD) + col] = make_float2(v0, v1);
                }
            }
        }
    }
}

// 32 queries per block (4 per warp). Lane-per-group argmax (first-max
// tie-break = jnp.argmax), accumulate group sums/counts, append to list.
__global__ void route_kernel(const float* __restrict__ w_gp) {
    __shared__ float sgp[GG][33];
    int tid = threadIdx.x;
    int w = tid >> 5, lane = tid & 31;
    int q0 = blockIdx.x * 32;          // NN % 32 == 0 -> whole block same bh
    int bh = q0 / NN;
    int h = bh % HH;
    for (int i = tid; i < GG*DD; i += 256)
        sgp[i >> 5][i & 31] = w_gp[h*GG*DD + i];
    __syncthreads();
    #pragma unroll
    for (int rep = 0; rep < 4; rep++) {
        int qid = q0 + rep*8 + w;
        int n = qid % NN;
        float qv = g_qkv[0][((size_t)bh*NN + n)*DD + lane];
        float s0 = 0.f, s1 = 0.f;
        #pragma unroll
        for (int d = 0; d < DD; d++) {
            float qd = __shfl_sync(0xffffffffu, qv, d);
            s0 += qd * sgp[lane][d];
            if (lane < 16) s1 += qd * sgp[lane + 32][d];
        }
        float bv = s0; int bg = lane;
        if (lane < 16 && (s1 > bv)) { bv = s1; bg = lane + 32; }
        #pragma unroll
        for (int o = 16; o; o >>= 1) {
            float ov = __shfl_xor_sync(0xffffffffu, bv, o);
            int   og = __shfl_xor_sync(0xffffffffu, bg, o);
            if (ov > bv || (ov == bv && og < bg)) { bv = ov; bg = og; }
        }
        bg = __shfl_sync(0xffffffffu, bg, 0);
        int row = bh*GG + bg;
        if (lane == 0) {
            g_gidx[qid] = bg;
            int p = atomicAdd(&g_cnt[row], 1);
            g_qlist[row*NN + p] = n;
        }
        atomicAdd(&g_qsum[row*DD + lane], qv);
    }
}

__device__ __forceinline__ unsigned f2u_mono(float f) {
    unsigned u = __float_as_uint(f);
    return u ^ (((int)u >> 31) | 0x80000000u);
}

// Grid (25, BHc): 64 keys per block; thread = (key, 12-group chunk).
__global__ void qmw_score_kernel() {
    __shared__ __align__(16) float qm[GG][DD];
    int bh = blockIdx.y;
    int n0 = blockIdx.x * 64;
    int tid = threadIdx.x;
    for (int i = tid; i < GG*DD; i += 256) {
        int g = i >> 5, d = i & 31;
        int row = bh*GG + g;
        float c = (float)g_cnt[row];
        qm[g][d] = g_qsum[row*DD + d] / fmaxf(c, 1e-8f);
    }
    __syncthreads();
    int key = tid & 63, gc = (tid >> 6) * 12;
    int m = n0 + key;
    const float* kb = &g_qkv[1][(size_t)bh*NN*DD];
    float kr[DD];
    #pragma unroll
    for (int t = 0; t < 8; t++) {
        float4 v = *(const float4*)(kb + (size_t)m*DD + 4*t);
        kr[4*t] = v.x; kr[4*t+1] = v.y; kr[4*t+2] = v.z; kr[4*t+3] = v.w;
    }
    float s[12];
    #pragma unroll
    for (int j = 0; j < 12; j++) s[j] = 0.f;
    #pragma unroll
    for (int t = 0; t < 8; t++) {
        #pragma unroll
        for (int j = 0; j < 12; j++) {
            float4 q = *(const float4*)&qm[gc + j][4*t];
            s[j] += q.x*kr[4*t] + q.y*kr[4*t+1] + q.z*kr[4*t+2] + q.w*kr[4*t+3];
        }
    }
    #pragma unroll
    for (int j = 0; j < 12; j++)
        g_scores[(size_t)(bh*GG + gc + j)*NN + m] = f2u_mono(s[j]);
}

// Fused: one block per (bh,g) row — radix-select top-96 (indices in smem),
// then stage K (key-major, 16B-aligned base+rows) + V and run attention with
// LDS.128-broadcast math. Empty rows exit immediately.
__global__ void select_attn_kernel() {
    int row = blockIdx.x;              // [0, NROW)
    int cnt = g_cnt[row];
    if (cnt == 0) return;

    __shared__ unsigned uv[NN];
    __shared__ unsigned hist[256];
    __shared__ int s_selb, s_k, s_nout;
    __shared__ int warp_sums[8];
    __shared__ int tk_s[KT];
    __shared__ __align__(16) float Kr[KT][36];   // [key][d], base+rows 16B-aligned
    __shared__ float Vs[KT][33];                 // [key][d] (scalar reads only)
    __shared__ __align__(16) float q_s[8][36];   // per-warp query vector
    __shared__ __align__(16) float p_s[8][100];  // per-warp softmax weights

    int tid = threadIdx.x, lane = tid & 31, w = tid >> 5;

    // ---- selection phase ----
    const unsigned* src = &g_scores[(size_t)row*NN];
    for (int m = tid; m < NN; m += 256) uv[m] = src[m];
    hist[tid] = 0;
    __syncthreads();

    unsigned prefix = 0;
    int k = KT;
    #pragma unroll
    for (int pass = 0; pass < 4; pass++) {
        int shift = 24 - 8*pass;
        for (int m = tid; m < NN; m += 256) {
            unsigned u = uv[m];
            bool cand = (pass == 0) || ((u >> (shift+8)) == (prefix >> (shift+8)));
            if (cand) atomicAdd(&hist[(u >> shift) & 255], 1u);
        }
        __syncthreads();
        if (tid < 32) {
            unsigned hv[8], loc[8];
            unsigned s = 0;
            #pragma unroll
            for (int i = 7; i >= 0; i--) {
                hv[i] = hist[lane*8 + i];
                s += hv[i];
                loc[i] = s;
            }
            unsigned run = s;
            #pragma unroll
            for (int o = 1; o < 32; o <<= 1) {
                unsigned t = __shfl_down_sync(0xffffffffu, run, o);
                if (lane + o < 32) run += t;
            }
            unsigned above = run - s;
            #pragma unroll
            for (int i = 0; i < 8; i++) {
                unsigned S  = above + loc[i];
                unsigned gt = S - hv[i];
                if ((unsigned)k <= S && (unsigned)k > gt) {
                    s_selb = lane*8 + i;
                    s_k    = k - (int)gt;
                }
            }
        }
        __syncthreads();
        prefix |= (unsigned)s_selb << shift;
        k = s_k;
        hist[tid] = 0;
        __syncthreads();
    }
    unsigned uT = prefix;
    int k_rem = k;
    if (tid == 0) s_nout = 0;
    __syncthreads();
    for (int m = tid; m < NN; m += 256) {
        if (uv[m] > uT) {
            int p = atomicAdd(&s_nout, 1);
            tk_s[p] = m;
        }
    }
    __syncthreads();
    int base = s_nout;
    const int CH = (NN + 255) / 256;
    int lo = tid * CH;
    int hi = lo + CH; if (hi > NN) hi = NN; if (lo > NN) lo = NN;
    int c_loc = 0;
    for (int m = lo; m < hi; m++) if (uv[m] == uT) c_loc++;
    int v = c_loc;
    #pragma unroll
    for (int o = 1; o < 32; o <<= 1) {
        int t = __shfl_up_sync(0xffffffffu, v, o);
        if (lane >= o) v += t;
    }
    if (lane == 31) warp_sums[w] = v;
    __syncthreads();
    int woff = 0;
    #pragma unroll
    for (int ww = 0; ww < 8; ww++) if (ww < w) woff += warp_sums[ww];
    int rank = woff + v - c_loc;
    for (int m = lo; m < hi; m++) {
        if (uv[m] == uT) {
            if (rank < k_rem) tk_s[base + rank] = m;
            rank++;
        }
    }
    __syncthreads();

    // ---- staging: K key-major + V key-major ----
    int bh = row / GG;
    int bi = bh / HH, h = bh % HH;
    const float* kb = &g_qkv[1][(size_t)bh*NN*DD];
    const float* vb = &g_qkv[2][(size_t)bh*NN*DD];
    for (int j = w; j < KT; j += 8) {
        int idx = tk_s[j];
        Kr[j][lane] = kb[(size_t)idx*DD + lane];
        Vs[j][lane] = vb[(size_t)idx*DD + lane];
    }
    __syncthreads();

    const int* ql = &g_qlist[row*NN];
    const float* qb = &g_qkv[0][(size_t)bh*NN*DD];
    const float scale = 0.17677669529663687f;  // 32^-0.5
    for (int i = w; i < cnt; i += 8) {
        int n = ql[i];
        // park q in smem
        q_s[w][lane] = qb[(size_t)n*DD + lane];
        __syncwarp();
        // scores: lane j handles keys j, j+32, j+64 via float4 broadcast q
        float s0 = 0.f, s1 = 0.f, s2 = 0.f;
        #pragma unroll
        for (int t = 0; t < 8; t++) {
            float4 q4 = *(const float4*)&q_s[w][4*t];
            float4 k0 = *(const float4*)&Kr[lane     ][4*t];
            float4 k1 = *(const float4*)&Kr[lane + 32][4*t];
            float4 k2 = *(const float4*)&Kr[lane + 64][4*t];
            s0 += q4.x*k0.x + q4.y*k0.y + q4.z*k0.z + q4.w*k0.w;
            s1 += q4.x*k1.x + q4.y*k1.y + q4.z*k1.z + q4.w*k1.w;
            s2 += q4.x*k2.x + q4.y*k2.y + q4.z*k2.z + q4.w*k2.w;
        }
        s0 *= scale; s1 *= scale; s2 *= scale;
        float mx = fmaxf(s0, fmaxf(s1, s2));
        #pragma unroll
        for (int o = 16; o; o >>= 1) mx = fmaxf(mx, __shfl_xor_sync(0xffffffffu, mx, o));
        float e0 = __expf(s0 - mx), e1 = __expf(s1 - mx), e2 = __expf(s2 - mx);
        float ps = e0 + e1 + e2;
        #pragma unroll
        for (int o = 16; o; o >>= 1) ps += __shfl_xor_sync(0xffffffffu, ps, o);
        float inv = 1.f / ps;
        // park p in smem
        p_s[w][lane]      = e0;
        p_s[w][lane + 32] = e1;
        p_s[w][lane + 64] = e2;
        __syncwarp();
        // PV: lane = d; float4 broadcast p, 4 partial accumulators
        float a0 = 0.f, a1 = 0.f, a2 = 0.f, a3 = 0.f;
        #pragma unroll
        for (int jj = 0; jj < KT/4; jj++) {
            float4 p4 = *(const float4*)&p_s[w][4*jj];
            a0 += p4.x * Vs[4*jj + 0][lane];
            a1 += p4.y * Vs[4*jj + 1][lane];
            a2 += p4.z * Vs[4*jj + 2][lane];
            a3 += p4.w * Vs[4*jj + 3][lane];
        }
        float acc = ((a0 + a1) + (a2 + a3)) * inv;
        g_att[(((size_t)bi*NN + n)*HH + h)*DD + lane] = acc;
        __syncwarp();
    }
}

extern "C" void kernel_launch(void* const* d_in, const int* in_sizes, int n_in,
                              void* d_out, int out_size) {
    const float* x      = (const float*)d_in[0];
    const float* w_qkv  = (const float*)d_in[1];
    const float* w_gp   = (const float*)d_in[2];
    const float* w_proj = (const float*)d_in[3];
    float* out = (float*)d_out;

    gemm_tf32<0><<<dim3(9, 25), 256>>>(x, w_qkv, nullptr);       // QKV (+ zero-init)
    route_kernel<<<NQ/32, 256>>>(w_gp);
    qmw_score_kernel<<<dim3(25, BHc), 256>>>();
    select_attn_kernel<<<NROW, 256>>>();
    gemm_tf32<1><<<dim3(3, 25), 256>>>(nullptr, w_proj, out);    // proj: 3200x384x384
}

// round 15
// speedup vs baseline: 1.2740x; 1.0759x over previous
#include <cuda_runtime.h>
#include <float.h>
#include <stdint.h>

#define BB 2
#define HH 12
#define NN 1600
#define DD 32
#define GG 48
#define KT 96
#define CC 384
#define BHc (BB*HH)          // 24
#define NQ (BHc*NN)          // 38400
#define NROW (BHc*GG)        // 1152

// Scratch (no cudaMalloc allowed)
__device__ float g_qkv[3][BHc*NN*DD];      // [which][b*h][n][d]
__device__ int   g_gidx[NQ];
__device__ float g_qsum[NROW*DD];
__device__ int   g_cnt[NROW];
__device__ int   g_qlist[NROW*NN];         // query indices per (bh,g)
__device__ float g_att[BB*NN*HH*DD];       // [b][n][h][d]
__device__ unsigned g_scores[NROW*NN];     // f2u-mapped qmw scores

// ---------------- 3xTF32 mma.sync GEMM (R7 version — do not touch core) -------
__device__ __forceinline__ uint32_t tf32_rna(float x) {
    uint32_t r; asm("cvt.rna.tf32.f32 %0, %1;" : "=r"(r) : "f"(x)); return r;
}
__device__ __forceinline__ void split_tf32(float x, uint32_t& h, uint32_t& l) {
    h = tf32_rna(x);
    l = tf32_rna(x - __uint_as_float(h));
}
__device__ __forceinline__ void mma8(float* c, const uint32_t* a, const uint32_t* b) {
    asm volatile(
        "mma.sync.aligned.m16n8k8.row.col.f32.tf32.tf32.f32 "
        "{%0,%1,%2,%3}, {%4,%5,%6,%7}, {%8,%9}, {%0,%1,%2,%3};"
        : "+f"(c[0]), "+f"(c[1]), "+f"(c[2]), "+f"(c[3])
        : "r"(a[0]), "r"(a[1]), "r"(a[2]), "r"(a[3]), "r"(b[0]), "r"(b[1]));
}

// out[m][col] = sum_k A[m][k] * B[col][k]   (NT, K=384)
// MODE 0: A = x, scatter into g_qkv; also zero-inits g_qsum/g_cnt.
// MODE 1: A = g_att, write d_out.
template<int MODE>
__global__ void __launch_bounds__(256, 1) gemm_tf32(const float* __restrict__ A,
                                                    const float* __restrict__ B,
                                                    float* __restrict__ out) {
    __shared__ __align__(16) float As[128][36];
    __shared__ __align__(16) float Bs[128][36];
    const int K = CC;
    const float* Ap = (MODE == 0) ? A : (const float*)g_att;
    int m0 = blockIdx.y * 128, n0 = blockIdx.x * 128;
    int tid = threadIdx.x, wid = tid >> 5, lane = tid & 31;
    int warpM = (wid >> 2) * 64;
    int warpN = (wid & 3) * 32;

    if (MODE == 0) {
        int zi = (blockIdx.y * 9 + blockIdx.x) * 256 + tid;
        if (zi < NROW*DD) g_qsum[zi] = 0.f;
        if (zi < NROW)    g_cnt[zi] = 0;
    }

    float acc[4][4][4];
    #pragma unroll
    for (int i = 0; i < 4; i++)
        #pragma unroll
        for (int j = 0; j < 4; j++)
            #pragma unroll
            for (int r = 0; r < 4; r++) acc[i][j][r] = 0.f;

    int srow = tid >> 3, sc4 = (tid & 7) << 2;
    for (int kt = 0; kt < K/32; kt++) {
        int k0 = kt * 32;
        #pragma unroll
        for (int it = 0; it < 4; it++) {
            int row = it*32 + srow;
            float4 va = *(const float4*)(Ap + (size_t)(m0 + row)*K + k0 + sc4);
            float4 vb = *(const float4*)(B  + (size_t)(n0 + row)*K + k0 + sc4);
            *(float4*)&As[row][sc4] = va;
            *(float4*)&Bs[row][sc4] = vb;
        }
        __syncthreads();
        #pragma unroll
        for (int kk = 0; kk < 4; kk++) {
            int c = kk*8 + (lane & 3);
            uint32_t ah[4][4], al[4][4], bh[4][2], bl[4][2];
            #pragma unroll
            for (int fm = 0; fm < 4; fm++) {
                int r = warpM + fm*16 + (lane >> 2);
                split_tf32(As[r    ][c    ], ah[fm][0], al[fm][0]);
                split_tf32(As[r + 8][c    ], ah[fm][1], al[fm][1]);
                split_tf32(As[r    ][c + 4], ah[fm][2], al[fm][2]);
                split_tf32(As[r + 8][c + 4], ah[fm][3], al[fm][3]);
            }
            #pragma unroll
            for (int fn = 0; fn < 4; fn++) {
                int n = warpN + fn*8 + (lane >> 2);
                split_tf32(Bs[n][c    ], bh[fn][0], bl[fn][0]);
                split_tf32(Bs[n][c + 4], bh[fn][1], bl[fn][1]);
            }
            #pragma unroll
            for (int fm = 0; fm < 4; fm++)
                #pragma unroll
                for (int fn = 0; fn < 4; fn++)
                    mma8(acc[fm][fn], ah[fm], bh[fn]);
            #pragma unroll
            for (int fm = 0; fm < 4; fm++)
                #pragma unroll
                for (int fn = 0; fn < 4; fn++)
                    mma8(acc[fm][fn], ah[fm], bl[fn]);
            #pragma unroll
            for (int fm = 0; fm < 4; fm++)
                #pragma unroll
                for (int fn = 0; fn < 4; fn++)
                    mma8(acc[fm][fn], al[fm], bh[fn]);
        }
        __syncthreads();
    }

    #pragma unroll
    for (int fm = 0; fm < 4; fm++) {
        #pragma unroll
        for (int half = 0; half < 2; half++) {
            int m = m0 + warpM + fm*16 + (lane >> 2) + half*8;
            int bi = m / NN, n = m % NN;
            #pragma unroll
            for (int fn = 0; fn < 4; fn++) {
                int col = n0 + warpN + fn*8 + 2*(lane & 3);
                float v0 = acc[fm][fn][half*2 + 0];
                float v1 = acc[fm][fn][half*2 + 1];
                if (MODE == 0) {
                    int which = col / (HH*DD);
                    int r2 = col % (HH*DD);
                    int head = r2 / DD, dd = r2 % DD;
                    float* dst = &g_qkv[which][(((size_t)bi*HH + head)*NN + n)*DD + dd];
                    *(float2*)dst = make_float2(v0, v1);
                } else {
                    *(float2*)&out[(size_t)m*(HH*DD) + col] = make_float2(v0, v1);
                }
            }
        }
    }
}

// 32 queries per block (4 per warp). Lane-per-group argmax (first-max
// tie-break = jnp.argmax), accumulate group sums/counts, append to list.
__global__ void route_kernel(const float* __restrict__ w_gp) {
    __shared__ float sgp[GG][33];
    int tid = threadIdx.x;
    int w = tid >> 5, lane = tid & 31;
    int q0 = blockIdx.x * 32;          // NN % 32 == 0 -> whole block same bh
    int bh = q0 / NN;
    int h = bh % HH;
    for (int i = tid; i < GG*DD; i += 256)
        sgp[i >> 5][i & 31] = w_gp[h*GG*DD + i];
    __syncthreads();
    #pragma unroll
    for (int rep = 0; rep < 4; rep++) {
        int qid = q0 + rep*8 + w;
        int n = qid % NN;
        float qv = g_qkv[0][((size_t)bh*NN + n)*DD + lane];
        float s0 = 0.f, s1 = 0.f;
        #pragma unroll
        for (int d = 0; d < DD; d++) {
            float qd = __shfl_sync(0xffffffffu, qv, d);
            s0 += qd * sgp[lane][d];
            if (lane < 16) s1 += qd * sgp[lane + 32][d];
        }
        float bv = s0; int bg = lane;
        if (lane < 16 && (s1 > bv)) { bv = s1; bg = lane + 32; }
        #pragma unroll
        for (int o = 16; o; o >>= 1) {
            float ov = __shfl_xor_sync(0xffffffffu, bv, o);
            int   og = __shfl_xor_sync(0xffffffffu, bg, o);
            if (ov > bv || (ov == bv && og < bg)) { bv = ov; bg = og; }
        }
        bg = __shfl_sync(0xffffffffu, bg, 0);
        int row = bh*GG + bg;
        if (lane == 0) {
            g_gidx[qid] = bg;
            int p = atomicAdd(&g_cnt[row], 1);
            g_qlist[row*NN + p] = n;
        }
        atomicAdd(&g_qsum[row*DD + lane], qv);
    }
}

__device__ __forceinline__ unsigned f2u_mono(float f) {
    unsigned u = __float_as_uint(f);
    return u ^ (((int)u >> 31) | 0x80000000u);
}

// Grid (25, BHc): 64 keys per block; thread = (key, 12-group chunk).
__global__ void qmw_score_kernel() {
    __shared__ __align__(16) float qm[GG][DD];
    int bh = blockIdx.y;
    int n0 = blockIdx.x * 64;
    int tid = threadIdx.x;
    for (int i = tid; i < GG*DD; i += 256) {
        int g = i >> 5, d = i & 31;
        int row = bh*GG + g;
        float c = (float)g_cnt[row];
        qm[g][d] = g_qsum[row*DD + d] / fmaxf(c, 1e-8f);
    }
    __syncthreads();
    int key = tid & 63, gc = (tid >> 6) * 12;
    int m = n0 + key;
    const float* kb = &g_qkv[1][(size_t)bh*NN*DD];
    float kr[DD];
    #pragma unroll
    for (int t = 0; t < 8; t++) {
        float4 v = *(const float4*)(kb + (size_t)m*DD + 4*t);
        kr[4*t] = v.x; kr[4*t+1] = v.y; kr[4*t+2] = v.z; kr[4*t+3] = v.w;
    }
    float s[12];
    #pragma unroll
    for (int j = 0; j < 12; j++) s[j] = 0.f;
    #pragma unroll
    for (int t = 0; t < 8; t++) {
        #pragma unroll
        for (int j = 0; j < 12; j++) {
            float4 q = *(const float4*)&qm[gc + j][4*t];
            s[j] += q.x*kr[4*t] + q.y*kr[4*t+1] + q.z*kr[4*t+2] + q.w*kr[4*t+3];
        }
    }
    #pragma unroll
    for (int j = 0; j < 12; j++)
        g_scores[(size_t)(bh*GG + gc + j)*NN + m] = f2u_mono(s[j]);
}

// Fused: one block per (bh,g) row — radix-select top-96 (indices in smem),
// then stage K (key-major) + V (d-major) and run attention 4-queries-per-warp
// with LDS.128-broadcast math. Empty rows exit immediately.
// ublk aliases: selection-phase uv[NN] vs attention-phase q/p buffers.
#define QS_BYTES (8*4*36*4)    // 4608
#define PS_BYTES (8*4*100*4)   // 12800
__global__ void select_attn_kernel() {
    int row = blockIdx.x;              // [0, NROW)
    int cnt = g_cnt[row];
    if (cnt == 0) return;

    __shared__ unsigned hist[256];
    __shared__ int s_selb, s_k, s_nout;
    __shared__ int warp_sums[8];
    __shared__ int tk_s[KT];
    __shared__ __align__(16) float Kr[KT][36];   // [key][d]
    __shared__ __align__(16) float Vt[DD][100];  // [d][key]
    __shared__ __align__(16) char ublk[QS_BYTES + PS_BYTES];  // uv | q_s+p_s

    unsigned* uv = (unsigned*)ublk;              // NN*4 = 6400 <= 17408

    int tid = threadIdx.x, lane = tid & 31, w = tid >> 5;

    // ---- selection phase ----
    const unsigned* src = &g_scores[(size_t)row*NN];
    for (int m = tid; m < NN; m += 256) uv[m] = src[m];
    hist[tid] = 0;
    __syncthreads();

    unsigned prefix = 0;
    int k = KT;
    #pragma unroll
    for (int pass = 0; pass < 4; pass++) {
        int shift = 24 - 8*pass;
        for (int m = tid; m < NN; m += 256) {
            unsigned u = uv[m];
            bool cand = (pass == 0) || ((u >> (shift+8)) == (prefix >> (shift+8)));
            if (cand) atomicAdd(&hist[(u >> shift) & 255], 1u);
        }
        __syncthreads();
        if (tid < 32) {
            unsigned hv[8], loc[8];
            unsigned s = 0;
            #pragma unroll
            for (int i = 7; i >= 0; i--) {
                hv[i] = hist[lane*8 + i];
                s += hv[i];
                loc[i] = s;
            }
            unsigned run = s;
            #pragma unroll
            for (int o = 1; o < 32; o <<= 1) {
                unsigned t = __shfl_down_sync(0xffffffffu, run, o);
                if (lane + o < 32) run += t;
            }
            unsigned above = run - s;
            #pragma unroll
            for (int i = 0; i < 8; i++) {
                unsigned S  = above + loc[i];
                unsigned gt = S - hv[i];
                if ((unsigned)k <= S && (unsigned)k > gt) {
                    s_selb = lane*8 + i;
                    s_k    = k - (int)gt;
                }
            }
        }
        __syncthreads();
        prefix |= (unsigned)s_selb << shift;
        k = s_k;
        hist[tid] = 0;
        __syncthreads();
    }
    unsigned uT = prefix;
    int k_rem = k;
    if (tid == 0) s_nout = 0;
    __syncthreads();
    for (int m = tid; m < NN; m += 256) {
        if (uv[m] > uT) {
            int p = atomicAdd(&s_nout, 1);
            tk_s[p] = m;
        }
    }
    __syncthreads();
    int base = s_nout;
    const int CH = (NN + 255) / 256;
    int lo = tid * CH;
    int hi = lo + CH; if (hi > NN) hi = NN; if (lo > NN) lo = NN;
    int c_loc = 0;
    for (int m = lo; m < hi; m++) if (uv[m] == uT) c_loc++;
    int v = c_loc;
    #pragma unroll
    for (int o = 1; o < 32; o <<= 1) {
        int t = __shfl_up_sync(0xffffffffu, v, o);
        if (lane >= o) v += t;
    }
    if (lane == 31) warp_sums[w] = v;
    __syncthreads();
    int woff = 0;
    #pragma unroll
    for (int ww = 0; ww < 8; ww++) if (ww < w) woff += warp_sums[ww];
    int rank = woff + v - c_loc;
    for (int m = lo; m < hi; m++) {
        if (uv[m] == uT) {
            if (rank < k_rem) tk_s[base + rank] = m;
            rank++;
        }
    }
    __syncthreads();                   // uv dead after this barrier

    // ---- staging: K key-major, V d-major ----
    int bh = row / GG;
    int bi = bh / HH, h = bh % HH;
    const float* kb = &g_qkv[1][(size_t)bh*NN*DD];
    const float* vb = &g_qkv[2][(size_t)bh*NN*DD];
    for (int j = w; j < KT; j += 8) {
        int idx = tk_s[j];
        Kr[j][lane] = kb[(size_t)idx*DD + lane];
        Vt[lane][j] = vb[(size_t)idx*DD + lane];
    }
    __syncthreads();

    float* q4s = (float*)ublk + w*4*36;              // [4][36]
    float* p4s = (float*)(ublk + QS_BYTES) + w*4*100; // [4][100]
    const int* ql = &g_qlist[row*NN];
    const float* qb = &g_qkv[0][(size_t)bh*NN*DD];
    const float scale = 0.17677669529663687f;  // 32^-0.5

    for (int i0 = 0; i0 < cnt; i0 += 32) {
        int qbase = i0 + w*4;
        #pragma unroll
        for (int qq = 0; qq < 4; qq++) {
            int qi = qbase + qq;
            float val = 0.f;
            if (qi < cnt) val = qb[(size_t)ql[qi]*DD + lane];
            q4s[qq*36 + lane] = val;
        }
        __syncwarp();
        // scores: lane j handles keys j, j+32, j+64 for all 4 queries
        float s[4][3];
        #pragma unroll
        for (int qq = 0; qq < 4; qq++) { s[qq][0] = 0.f; s[qq][1] = 0.f; s[qq][2] = 0.f; }
        #pragma unroll
        for (int t = 0; t < 8; t++) {
            float4 k0 = *(const float4*)&Kr[lane     ][4*t];
            float4 k1 = *(const float4*)&Kr[lane + 32][4*t];
            float4 k2 = *(const float4*)&Kr[lane + 64][4*t];
            #pragma unroll
            for (int qq = 0; qq < 4; qq++) {
                float4 q4 = *(const float4*)&q4s[qq*36 + 4*t];
                s[qq][0] += q4.x*k0.x + q4.y*k0.y + q4.z*k0.z + q4.w*k0.w;
                s[qq][1] += q4.x*k1.x + q4.y*k1.y + q4.z*k1.z + q4.w*k1.w;
                s[qq][2] += q4.x*k2.x + q4.y*k2.y + q4.z*k2.z + q4.w*k2.w;
            }
        }
        float inv[4];
        #pragma unroll
        for (int qq = 0; qq < 4; qq++) {
            float s0 = s[qq][0]*scale, s1 = s[qq][1]*scale, s2 = s[qq][2]*scale;
            float mx = fmaxf(s0, fmaxf(s1, s2));
            #pragma unroll
            for (int o = 16; o; o >>= 1) mx = fmaxf(mx, __shfl_xor_sync(0xffffffffu, mx, o));
            float e0 = __expf(s0 - mx), e1 = __expf(s1 - mx), e2 = __expf(s2 - mx);
            float ps = e0 + e1 + e2;
            #pragma unroll
            for (int o = 16; o; o >>= 1) ps += __shfl_xor_sync(0xffffffffu, ps, o);
            inv[qq] = 1.f / ps;
            p4s[qq*100 + lane]      = e0;
            p4s[qq*100 + lane + 32] = e1;
            p4s[qq*100 + lane + 64] = e2;
        }
        __syncwarp();
        // PV: lane = d; V column contiguous float4, p broadcast float4
        float a[4] = {0.f, 0.f, 0.f, 0.f};
        #pragma unroll
        for (int jj = 0; jj < KT/4; jj++) {
            float4 v4 = *(const float4*)&Vt[lane][4*jj];
            #pragma unroll
            for (int qq = 0; qq < 4; qq++) {
                float4 p4 = *(const float4*)&p4s[qq*100 + 4*jj];
                a[qq] += p4.x*v4.x + p4.y*v4.y + p4.z*v4.z + p4.w*v4.w;
            }
        }
        #pragma unroll
        for (int qq = 0; qq < 4; qq++) {
            int qi = qbase + qq;
            if (qi < cnt) {
                int n = ql[qi];
                g_att[(((size_t)bi*NN + n)*HH + h)*DD + lane] = a[qq] * inv[qq];
            }
        }
        __syncwarp();
    }
}

extern "C" void kernel_launch(void* const* d_in, const int* in_sizes, int n_in,
                              void* d_out, int out_size) {
    const float* x      = (const float*)d_in[0];
    const float* w_qkv  = (const float*)d_in[1];
    const float* w_gp   = (const float*)d_in[2];
    const float* w_proj = (const float*)d_in[3];
    float* out = (float*)d_out;

    gemm_tf32<0><<<dim3(9, 25), 256>>>(x, w_qkv, nullptr);       // QKV (+ zero-init)
    route_kernel<<<NQ/32, 256>>>(w_gp);
    qmw_score_kernel<<<dim3(25, BHc), 256>>>();
    select_attn_kernel<<<NROW, 256>>>();
    gemm_tf32<1><<<dim3(3, 25), 256>>>(nullptr, w_proj, out);    // proj: 3200x384x384
}

// round 16
// speedup vs baseline: 1.3031x; 1.0228x over previous
#include <cuda_runtime.h>
#include <float.h>
#include <stdint.h>

#define BB 2
#define HH 12
#define NN 1600
#define DD 32
#define GG 48
#define KT 96
#define CC 384
#define BHc (BB*HH)          // 24
#define NQ (BHc*NN)          // 38400
#define NROW (BHc*GG)        // 1152

// Scratch (no cudaMalloc allowed)
__device__ float g_qkv[3][BHc*NN*DD];      // [which][b*h][n][d]
__device__ int   g_gidx[NQ];
__device__ float g_qsum[NROW*DD];
__device__ int   g_cnt[NROW];
__device__ int   g_qlist[NROW*NN];         // query indices per (bh,g)
__device__ float g_att[BB*NN*HH*DD];       // [b][n][h][d]
__device__ unsigned g_scores[NROW*NN];     // f2u-mapped qmw scores

// ---------------- 3xTF32 mma.sync GEMM (R7 math — occupancy knob only) -------
__device__ __forceinline__ uint32_t tf32_rna(float x) {
    uint32_t r; asm("cvt.rna.tf32.f32 %0, %1;" : "=r"(r) : "f"(x)); return r;
}
__device__ __forceinline__ void split_tf32(float x, uint32_t& h, uint32_t& l) {
    h = tf32_rna(x);
    l = tf32_rna(x - __uint_as_float(h));
}
__device__ __forceinline__ void mma8(float* c, const uint32_t* a, const uint32_t* b) {
    asm volatile(
        "mma.sync.aligned.m16n8k8.row.col.f32.tf32.tf32.f32 "
        "{%0,%1,%2,%3}, {%4,%5,%6,%7}, {%8,%9}, {%0,%1,%2,%3};"
        : "+f"(c[0]), "+f"(c[1]), "+f"(c[2]), "+f"(c[3])
        : "r"(a[0]), "r"(a[1]), "r"(a[2]), "r"(a[3]), "r"(b[0]), "r"(b[1]));
}

// out[m][col] = sum_k A[m][k] * B[col][k]   (NT, K=384)
// MODE 0: A = x, scatter into g_qkv; also zero-inits g_qsum/g_cnt.
// MODE 1: A = g_att, write d_out.
template<int MODE>
__global__ void __launch_bounds__(256, 2) gemm_tf32(const float* __restrict__ A,
                                                    const float* __restrict__ B,
                                                    float* __restrict__ out) {
    __shared__ __align__(16) float As[128][36];
    __shared__ __align__(16) float Bs[128][36];
    const int K = CC;
    const float* Ap = (MODE == 0) ? A : (const float*)g_att;
    int m0 = blockIdx.y * 128, n0 = blockIdx.x * 128;
    int tid = threadIdx.x, wid = tid >> 5, lane = tid & 31;
    int warpM = (wid >> 2) * 64;
    int warpN = (wid & 3) * 32;

    if (MODE == 0) {
        int zi = (blockIdx.y * 9 + blockIdx.x) * 256 + tid;
        if (zi < NROW*DD) g_qsum[zi] = 0.f;
        if (zi < NROW)    g_cnt[zi] = 0;
    }

    float acc[4][4][4];
    #pragma unroll
    for (int i = 0; i < 4; i++)
        #pragma unroll
        for (int j = 0; j < 4; j++)
            #pragma unroll
            for (int r = 0; r < 4; r++) acc[i][j][r] = 0.f;

    int srow = tid >> 3, sc4 = (tid & 7) << 2;
    for (int kt = 0; kt < K/32; kt++) {
        int k0 = kt * 32;
        #pragma unroll
        for (int it = 0; it < 4; it++) {
            int row = it*32 + srow;
            float4 va = *(const float4*)(Ap + (size_t)(m0 + row)*K + k0 + sc4);
            float4 vb = *(const float4*)(B  + (size_t)(n0 + row)*K + k0 + sc4);
            *(float4*)&As[row][sc4] = va;
            *(float4*)&Bs[row][sc4] = vb;
        }
        __syncthreads();
        #pragma unroll
        for (int kk = 0; kk < 4; kk++) {
            int c = kk*8 + (lane & 3);
            uint32_t ah[4][4], al[4][4], bh[4][2], bl[4][2];
            #pragma unroll
            for (int fm = 0; fm < 4; fm++) {
                int r = warpM + fm*16 + (lane >> 2);
                split_tf32(As[r    ][c    ], ah[fm][0], al[fm][0]);
                split_tf32(As[r + 8][c    ], ah[fm][1], al[fm][1]);
                split_tf32(As[r    ][c + 4], ah[fm][2], al[fm][2]);
                split_tf32(As[r + 8][c + 4], ah[fm][3], al[fm][3]);
            }
            #pragma unroll
            for (int fn = 0; fn < 4; fn++) {
                int n = warpN + fn*8 + (lane >> 2);
                split_tf32(Bs[n][c    ], bh[fn][0], bl[fn][0]);
                split_tf32(Bs[n][c + 4], bh[fn][1], bl[fn][1]);
            }
            #pragma unroll
            for (int fm = 0; fm < 4; fm++)
                #pragma unroll
                for (int fn = 0; fn < 4; fn++)
                    mma8(acc[fm][fn], ah[fm], bh[fn]);
            #pragma unroll
            for (int fm = 0; fm < 4; fm++)
                #pragma unroll
                for (int fn = 0; fn < 4; fn++)
                    mma8(acc[fm][fn], ah[fm], bl[fn]);
            #pragma unroll
            for (int fm = 0; fm < 4; fm++)
                #pragma unroll
                for (int fn = 0; fn < 4; fn++)
                    mma8(acc[fm][fn], al[fm], bh[fn]);
        }
        __syncthreads();
    }

    #pragma unroll
    for (int fm = 0; fm < 4; fm++) {
        #pragma unroll
        for (int half = 0; half < 2; half++) {
            int m = m0 + warpM + fm*16 + (lane >> 2) + half*8;
            int bi = m / NN, n = m % NN;
            #pragma unroll
            for (int fn = 0; fn < 4; fn++) {
                int col = n0 + warpN + fn*8 + 2*(lane & 3);
                float v0 = acc[fm][fn][half*2 + 0];
                float v1 = acc[fm][fn][half*2 + 1];
                if (MODE == 0) {
                    int which = col / (HH*DD);
                    int r2 = col % (HH*DD);
                    int head = r2 / DD, dd = r2 % DD;
                    float* dst = &g_qkv[which][(((size_t)bi*HH + head)*NN + n)*DD + dd];
                    *(float2*)dst = make_float2(v0, v1);
                } else {
                    *(float2*)&out[(size_t)m*(HH*DD) + col] = make_float2(v0, v1);
                }
            }
        }
    }
}

// 32 queries per block (4 per warp). Lane-per-group argmax (first-max
// tie-break = jnp.argmax), accumulate group sums/counts, append to list.
__global__ void route_kernel(const float* __restrict__ w_gp) {
    __shared__ float sgp[GG][33];
    int tid = threadIdx.x;
    int w = tid >> 5, lane = tid & 31;
    int q0 = blockIdx.x * 32;          // NN % 32 == 0 -> whole block same bh
    int bh = q0 / NN;
    int h = bh % HH;
    for (int i = tid; i < GG*DD; i += 256)
        sgp[i >> 5][i & 31] = w_gp[h*GG*DD + i];
    __syncthreads();
    #pragma unroll
    for (int rep = 0; rep < 4; rep++) {
        int qid = q0 + rep*8 + w;
        int n = qid % NN;
        float qv = g_qkv[0][((size_t)bh*NN + n)*DD + lane];
        float s0 = 0.f, s1 = 0.f;
        #pragma unroll
        for (int d = 0; d < DD; d++) {
            float qd = __shfl_sync(0xffffffffu, qv, d);
            s0 += qd * sgp[lane][d];
            if (lane < 16) s1 += qd * sgp[lane + 32][d];
        }
        float bv = s0; int bg = lane;
        if (lane < 16 && (s1 > bv)) { bv = s1; bg = lane + 32; }
        #pragma unroll
        for (int o = 16; o; o >>= 1) {
            float ov = __shfl_xor_sync(0xffffffffu, bv, o);
            int   og = __shfl_xor_sync(0xffffffffu, bg, o);
            if (ov > bv || (ov == bv && og < bg)) { bv = ov; bg = og; }
        }
        bg = __shfl_sync(0xffffffffu, bg, 0);
        int row = bh*GG + bg;
        if (lane == 0) {
            g_gidx[qid] = bg;
            int p = atomicAdd(&g_cnt[row], 1);
            g_qlist[row*NN + p] = n;
        }
        atomicAdd(&g_qsum[row*DD + lane], qv);
    }
}

__device__ __forceinline__ unsigned f2u_mono(float f) {
    unsigned u = __float_as_uint(f);
    return u ^ (((int)u >> 31) | 0x80000000u);
}

// Grid (25, BHc): 64 keys per block; thread = (key, 12-group chunk).
__global__ void qmw_score_kernel() {
    __shared__ __align__(16) float qm[GG][DD];
    int bh = blockIdx.y;
    int n0 = blockIdx.x * 64;
    int tid = threadIdx.x;
    for (int i = tid; i < GG*DD; i += 256) {
        int g = i >> 5, d = i & 31;
        int row = bh*GG + g;
        float c = (float)g_cnt[row];
        qm[g][d] = g_qsum[row*DD + d] / fmaxf(c, 1e-8f);
    }
    __syncthreads();
    int key = tid & 63, gc = (tid >> 6) * 12;
    int m = n0 + key;
    const float* kb = &g_qkv[1][(size_t)bh*NN*DD];
    float kr[DD];
    #pragma unroll
    for (int t = 0; t < 8; t++) {
        float4 v = *(const float4*)(kb + (size_t)m*DD + 4*t);
        kr[4*t] = v.x; kr[4*t+1] = v.y; kr[4*t+2] = v.z; kr[4*t+3] = v.w;
    }
    float s[12];
    #pragma unroll
    for (int j = 0; j < 12; j++) s[j] = 0.f;
    #pragma unroll
    for (int t = 0; t < 8; t++) {
        #pragma unroll
        for (int j = 0; j < 12; j++) {
            float4 q = *(const float4*)&qm[gc + j][4*t];
            s[j] += q.x*kr[4*t] + q.y*kr[4*t+1] + q.z*kr[4*t+2] + q.w*kr[4*t+3];
        }
    }
    #pragma unroll
    for (int j = 0; j < 12; j++)
        g_scores[(size_t)(bh*GG + gc + j)*NN + m] = f2u_mono(s[j]);
}

// Fused select+attn: candidate-compressed radix top-96, then 4-queries-per-warp
// attention with LDS.128-broadcast math. Empty rows exit immediately.
// ublk aliases: selection-phase uv[NN]+cand[NN]  vs  attention-phase q/p buffers.
#define QS_BYTES (8*4*36*4)    // 4608
#define PS_BYTES (8*4*100*4)   // 12800
__global__ void select_attn_kernel() {
    int row = blockIdx.x;              // [0, NROW)
    int cnt = g_cnt[row];
    if (cnt == 0) return;

    __shared__ unsigned hist[256];
    __shared__ int s_selb, s_k, s_nout, s_ncand;
    __shared__ int warp_sums[8];
    __shared__ int tk_s[KT];
    __shared__ __align__(16) float Kr[KT][36];   // [key][d]
    __shared__ __align__(16) float Vt[DD][100];  // [d][key]
    __shared__ __align__(16) char ublk[QS_BYTES + PS_BYTES];  // uv+cand | q_s+p_s

    unsigned* uv   = (unsigned*)ublk;            // [0, 6400)
    int*      cand = (int*)(ublk + NN*4);        // [6400, 12800)

    int tid = threadIdx.x, lane = tid & 31, w = tid >> 5;

    // ---- selection phase ----
    const unsigned* src = &g_scores[(size_t)row*NN];
    for (int m = tid; m < NN; m += 256) uv[m] = src[m];
    hist[tid] = 0;
    __syncthreads();

    // pass 0: full histogram over top byte
    int k = KT;
    for (int m = tid; m < NN; m += 256)
        atomicAdd(&hist[uv[m] >> 24], 1u);
    __syncthreads();
    if (tid < 32) {
        unsigned hv[8], loc[8];
        unsigned s = 0;
        #pragma unroll
        for (int i = 7; i >= 0; i--) { hv[i] = hist[lane*8 + i]; s += hv[i]; loc[i] = s; }
        unsigned run = s;
        #pragma unroll
        for (int o = 1; o < 32; o <<= 1) {
            unsigned t = __shfl_down_sync(0xffffffffu, run, o);
            if (lane + o < 32) run += t;
        }
        unsigned above = run - s;
        #pragma unroll
        for (int i = 0; i < 8; i++) {
            unsigned S  = above + loc[i];
            unsigned gt = S - hv[i];
            if ((unsigned)k <= S && (unsigned)k > gt) { s_selb = lane*8 + i; s_k = k - (int)gt; }
        }
    }
    if (tid == 0) { s_nout = 0; s_ncand = 0; }
    __syncthreads();
    unsigned selb0 = (unsigned)s_selb;
    unsigned prefix = selb0 << 24;
    k = s_k;
    hist[tid] = 0;
    __syncthreads();

    // emit byte0-greater directly; collect byte0-equal candidates
    for (int m = tid; m < NN; m += 256) {
        unsigned b = uv[m] >> 24;
        if (b > selb0) {
            int p = atomicAdd(&s_nout, 1);
            tk_s[p] = m;
        } else if (b == selb0) {
            int p = atomicAdd(&s_ncand, 1);
            cand[p] = m;
        }
    }
    __syncthreads();
    int ncand = s_ncand;

    // passes 1-3: candidates only
    #pragma unroll
    for (int pass = 1; pass < 4; pass++) {
        int shift = 24 - 8*pass;
        for (int i = tid; i < ncand; i += 256) {
            unsigned u = uv[cand[i]];
            if ((u >> (shift+8)) == (prefix >> (shift+8)))
                atomicAdd(&hist[(u >> shift) & 255], 1u);
        }
        __syncthreads();
        if (tid < 32) {
            unsigned hv[8], loc[8];
            unsigned s = 0;
            #pragma unroll
            for (int i = 7; i >= 0; i--) { hv[i] = hist[lane*8 + i]; s += hv[i]; loc[i] = s; }
            unsigned run = s;
            #pragma unroll
            for (int o = 1; o < 32; o <<= 1) {
                unsigned t = __shfl_down_sync(0xffffffffu, run, o);
                if (lane + o < 32) run += t;
            }
            unsigned above = run - s;
            #pragma unroll
            for (int i = 0; i < 8; i++) {
                unsigned S  = above + loc[i];
                unsigned gt = S - hv[i];
                if ((unsigned)k <= S && (unsigned)k > gt) { s_selb = lane*8 + i; s_k = k - (int)gt; }
            }
        }
        __syncthreads();
        prefix |= (unsigned)s_selb << shift;
        k = s_k;
        hist[tid] = 0;
        __syncthreads();
    }
    unsigned uT = prefix;
    int k_rem = k;
    // remaining strictly-greater among candidates
    for (int i = tid; i < ncand; i += 256) {
        int m = cand[i];
        if (uv[m] > uT) {
            int p = atomicAdd(&s_nout, 1);
            tk_s[p] = m;
        }
    }
    __syncthreads();
    int base = s_nout;                 // == KT - k_rem
    // equals: keep the k_rem LOWEST indices (full in-order scan, unchanged)
    const int CH = (NN + 255) / 256;   // 7
    int lo = tid * CH;
    int hi = lo + CH; if (hi > NN) hi = NN; if (lo > NN) lo = NN;
    int c_loc = 0;
    for (int m = lo; m < hi; m++) if (uv[m] == uT) c_loc++;
    int v = c_loc;
    #pragma unroll
    for (int o = 1; o < 32; o <<= 1) {
        int t = __shfl_up_sync(0xffffffffu, v, o);
        if (lane >= o) v += t;
    }
    if (lane == 31) warp_sums[w] = v;
    __syncthreads();
    int woff = 0;
    #pragma unroll
    for (int ww = 0; ww < 8; ww++) if (ww < w) woff += warp_sums[ww];
    int rank = woff + v - c_loc;
    for (int m = lo; m < hi; m++) {
        if (uv[m] == uT) {
            if (rank < k_rem) tk_s[base + rank] = m;
            rank++;
        }
    }
    __syncthreads();                   // uv/cand dead after this barrier

    // ---- staging: K key-major, V d-major ----
    int bh = row / GG;
    int bi = bh / HH, h = bh % HH;
    const float* kb = &g_qkv[1][(size_t)bh*NN*DD];
    const float* vb = &g_qkv[2][(size_t)bh*NN*DD];
    for (int j = w; j < KT; j += 8) {
        int idx = tk_s[j];
        Kr[j][lane] = kb[(size_t)idx*DD + lane];
        Vt[lane][j] = vb[(size_t)idx*DD + lane];
    }
    __syncthreads();

    float* q4s = (float*)ublk + w*4*36;               // [4][36]
    float* p4s = (float*)(ublk + QS_BYTES) + w*4*100; // [4][100]
    const int* ql = &g_qlist[row*NN];
    const float* qb = &g_qkv[0][(size_t)bh*NN*DD];
    const float scale = 0.17677669529663687f;  // 32^-0.5

    for (int i0 = 0; i0 < cnt; i0 += 32) {
        int qbase = i0 + w*4;
        #pragma unroll
        for (int qq = 0; qq < 4; qq++) {
            int qi = qbase + qq;
            float val = 0.f;
            if (qi < cnt) val = qb[(size_t)ql[qi]*DD + lane];
            q4s[qq*36 + lane] = val;
        }
        __syncwarp();
        float s[4][3];
        #pragma unroll
        for (int qq = 0; qq < 4; qq++) { s[qq][0] = 0.f; s[qq][1] = 0.f; s[qq][2] = 0.f; }
        #pragma unroll
        for (int t = 0; t < 8; t++) {
            float4 k0 = *(const float4*)&Kr[lane     ][4*t];
            float4 k1 = *(const float4*)&Kr[lane + 32][4*t];
            float4 k2 = *(const float4*)&Kr[lane + 64][4*t];
            #pragma unroll
            for (int qq = 0; qq < 4; qq++) {
                float4 q4 = *(const float4*)&q4s[qq*36 + 4*t];
                s[qq][0] += q4.x*k0.x + q4.y*k0.y + q4.z*k0.z + q4.w*k0.w;
                s[qq][1] += q4.x*k1.x + q4.y*k1.y + q4.z*k1.z + q4.w*k1.w;
                s[qq][2] += q4.x*k2.x + q4.y*k2.y + q4.z*k2.z + q4.w*k2.w;
            }
        }
        float inv[4];
        #pragma unroll
        for (int qq = 0; qq < 4; qq++) {
            float s0 = s[qq][0]*scale, s1 = s[qq][1]*scale, s2 = s[qq][2]*scale;
            float mx = fmaxf(s0, fmaxf(s1, s2));
            #pragma unroll
            for (int o = 16; o; o >>= 1) mx = fmaxf(mx, __shfl_xor_sync(0xffffffffu, mx, o));
            float e0 = __expf(s0 - mx), e1 = __expf(s1 - mx), e2 = __expf(s2 - mx);
            float ps = e0 + e1 + e2;
            #pragma unroll
            for (int o = 16; o; o >>= 1) ps += __shfl_xor_sync(0xffffffffu, ps, o);
            inv[qq] = 1.f / ps;
            p4s[qq*100 + lane]      = e0;
            p4s[qq*100 + lane + 32] = e1;
            p4s[qq*100 + lane + 64] = e2;
        }
        __syncwarp();
        float a[4] = {0.f, 0.f, 0.f, 0.f};
        #pragma unroll
        for (int jj = 0; jj < KT/4; jj++) {
            float4 v4 = *(const float4*)&Vt[lane][4*jj];
            #pragma unroll
            for (int qq = 0; qq < 4; qq++) {
                float4 p4 = *(const float4*)&p4s[qq*100 + 4*jj];
                a[qq] += p4.x*v4.x + p4.y*v4.y + p4.z*v4.z + p4.w*v4.w;
            }
        }
        #pragma unroll
        for (int qq = 0; qq < 4; qq++) {
            int qi = qbase + qq;
            if (qi < cnt) {
                int n = ql[qi];
                g_att[(((size_t)bi*NN + n)*HH + h)*DD + lane] = a[qq] * inv[qq];
            }
        }
        __syncwarp();
    }
}

extern "C" void kernel_launch(void* const* d_in, const int* in_sizes, int n_in,
                              void* d_out, int out_size) {
    const float* x      = (const float*)d_in[0];
    const float* w_qkv  = (const float*)d_in[1];
    const float* w_gp   = (const float*)d_in[2];
    const float* w_proj = (const float*)d_in[3];
    float* out = (float*)d_out;

    gemm_tf32<0><<<dim3(9, 25), 256>>>(x, w_qkv, nullptr);       // QKV (+ zero-init)
    route_kernel<<<NQ/32, 256>>>(w_gp);
    qmw_score_kernel<<<dim3(25, BHc), 256>>>();
    select_attn_kernel<<<NROW, 256>>>();
    gemm_tf32<1><<<dim3(3, 25), 256>>>(nullptr, w_proj, out);    // proj: 3200x384x384
}